// round 13
// baseline (speedup 1.0000x reference)
#include <cuda_runtime.h>
#include <cuda_bf16.h>
#include <math.h>
#include <stdint.h>

#define SEQ   2048
#define ND    1024
#define NH    16
#define DH    64
#define NPOS  64

typedef __nv_bfloat16 bf16;
typedef __nv_bfloat162 bf162;

// ---------------- scratch (device globals: allocation-free) ----------------
__device__ float g_Q[SEQ * ND];
__device__ float g_logits[(size_t)NH * SEQ * SEQ];    // 256 MB fp32 logits
__device__ float g_li[NH * SEQ * NPOS];

__device__ bf16 g_inqh[SEQ * ND], g_inql[SEQ * ND];
__device__ bf16 g_inkh[SEQ * ND], g_inkl[SEQ * ND];
__device__ bf16 g_invh[SEQ * ND], g_invl[SEQ * ND];
__device__ bf16 g_wqh[ND * ND], g_wql[ND * ND];
__device__ bf16 g_wkh[ND * ND], g_wkl[ND * ND];
__device__ bf16 g_wvh[ND * ND], g_wvl[ND * ND];
__device__ bf16 g_woh[ND * ND], g_wol[ND * ND];
__device__ bf16 g_Qh[SEQ * ND], g_Ql[SEQ * ND];
__device__ bf16 g_Kh[SEQ * ND], g_Kl[SEQ * ND];
__device__ bf16 g_Vh[SEQ * ND], g_Vl[SEQ * ND];
__device__ bf16 g_ctxh[SEQ * ND], g_ctxl[SEQ * ND];
__device__ bf16 g_Sh[(size_t)NH * SEQ * SEQ];
__device__ bf16 g_Sl[(size_t)NH * SEQ * SEQ];

// ---------------- PTX helpers ----------------------------------------------
__device__ __forceinline__ uint32_t smem_u32(const void* p) {
    return (uint32_t)__cvta_generic_to_shared(p);
}
__device__ __forceinline__ void ldsm4(uint32_t* r, uint32_t a) {
    asm volatile("ldmatrix.sync.aligned.m8n8.x4.shared.b16 {%0,%1,%2,%3}, [%4];"
                 : "=r"(r[0]), "=r"(r[1]), "=r"(r[2]), "=r"(r[3]) : "r"(a));
}
__device__ __forceinline__ void ldsm4t(uint32_t* r, uint32_t a) {
    asm volatile("ldmatrix.sync.aligned.m8n8.x4.trans.shared.b16 {%0,%1,%2,%3}, [%4];"
                 : "=r"(r[0]), "=r"(r[1]), "=r"(r[2]), "=r"(r[3]) : "r"(a));
}
__device__ __forceinline__ void mma16816(float* c, const uint32_t* a, const uint32_t* b) {
    asm volatile(
        "mma.sync.aligned.m16n8k16.row.col.f32.bf16.bf16.f32 "
        "{%0,%1,%2,%3}, {%4,%5,%6,%7}, {%8,%9}, {%0,%1,%2,%3};"
        : "+f"(c[0]), "+f"(c[1]), "+f"(c[2]), "+f"(c[3])
        : "r"(a[0]), "r"(a[1]), "r"(a[2]), "r"(a[3]), "r"(b[0]), "r"(b[1]));
}
__device__ __forceinline__ void cp16(uint32_t sa, const void* g) {
    asm volatile("cp.async.cg.shared.global [%0], [%1], 16;" :: "r"(sa), "l"(g));
}
#define CP_COMMIT() asm volatile("cp.async.commit_group;" ::: "memory")
#define CP_WAIT1()  asm volatile("cp.async.wait_group 1;" ::: "memory")
#define CP_WAIT0()  asm volatile("cp.async.wait_group 0;" ::: "memory")

// ---------------- split fp32 -> bf16 hi + bf16 lo (batched) -----------------
__device__ __forceinline__ void split_body(const float* __restrict__ s,
                                           bf16* __restrict__ hi, bf16* __restrict__ lo)
{
    int i = (blockIdx.x * 256 + threadIdx.x) * 4;
    float4 v = *(const float4*)&s[i];
    bf16 h0 = __float2bfloat16_rn(v.x), h1 = __float2bfloat16_rn(v.y);
    bf16 h2 = __float2bfloat16_rn(v.z), h3 = __float2bfloat16_rn(v.w);
    bf16 l0 = __float2bfloat16_rn(v.x - __bfloat162float(h0));
    bf16 l1 = __float2bfloat16_rn(v.y - __bfloat162float(h1));
    bf16 l2 = __float2bfloat16_rn(v.z - __bfloat162float(h2));
    bf16 l3 = __float2bfloat16_rn(v.w - __bfloat162float(h3));
    *(bf162*)&hi[i]     = bf162{h0, h1};
    *(bf162*)&hi[i + 2] = bf162{h2, h3};
    *(bf162*)&lo[i]     = bf162{l0, l1};
    *(bf162*)&lo[i + 2] = bf162{l2, l3};
}

__global__ __launch_bounds__(256) void split3_kernel(
    const float* s0, const float* s1, const float* s2,
    bf16* h0, bf16* l0, bf16* h1, bf16* l1, bf16* h2, bf16* l2)
{
    const float* s = (blockIdx.y == 0) ? s0 : (blockIdx.y == 1) ? s1 : s2;
    bf16* hp = (blockIdx.y == 0) ? h0 : (blockIdx.y == 1) ? h1 : h2;
    bf16* lp = (blockIdx.y == 0) ? l0 : (blockIdx.y == 1) ? l1 : l2;
    split_body(s, hp, lp);
}

__global__ __launch_bounds__(256) void split4_kernel(
    const float* s0, const float* s1, const float* s2, const float* s3,
    bf16* h0, bf16* l0, bf16* h1, bf16* l1,
    bf16* h2, bf16* l2, bf16* h3, bf16* l3)
{
    const float* s = (blockIdx.y == 0) ? s0 : (blockIdx.y == 1) ? s1 :
                     (blockIdx.y == 2) ? s2 : s3;
    bf16* hp = (blockIdx.y == 0) ? h0 : (blockIdx.y == 1) ? h1 :
               (blockIdx.y == 2) ? h2 : h3;
    bf16* lp = (blockIdx.y == 0) ? l0 : (blockIdx.y == 1) ? l1 :
               (blockIdx.y == 2) ? l2 : l3;
    split_body(s, hp, lp);
}

// ---------------- Y = X @ W^T + bias (split-bf16, cp.async 2-stage) ---------
// Block 128(m) x 64(n), BK=32, 4 warps (warp tile 32x64). 3 CTAs/SM.
#define MMST 40
#define MM_XH 0
#define MM_XL (128 * MMST)
#define MM_WH (256 * MMST)
#define MM_WL (320 * MMST)
#define MM_STAGE (384 * MMST)            // elems per stage
#define MM_SMEM  (2 * MM_STAGE * 2)      // 61440 bytes

__global__ __launch_bounds__(128, 3) void mm_bias_kernel(
    const bf16* __restrict__ Xh, const bf16* __restrict__ Xl,
    const bf16* __restrict__ Wh, const bf16* __restrict__ Wl,
    const float* __restrict__ bias,
    float* __restrict__ Yf, bf16* __restrict__ Yh, bf16* __restrict__ Yl)
{
    extern __shared__ bf16 mms[];
    const int tid = threadIdx.x, lane = tid & 31, warp = tid >> 5;
    const int m0 = blockIdx.y * 128, n0 = blockIdx.x * 64;
    const int wr = tid & 63;             // W row for loader

    // loader: thread t owns X row t (4 cp16 hi + 4 lo) and W row t&63 (hi if t<64 else lo)
    #define MM_LOAD(kt, s)                                                        \
        { bf16* st = mms + (s) * MM_STAGE;                                        \
          const bf16* gxh = &Xh[(size_t)(m0 + tid) * ND + (kt)];                  \
          const bf16* gxl = &Xl[(size_t)(m0 + tid) * ND + (kt)];                  \
          const bf16* gw  = (tid < 64) ? &Wh[(size_t)(n0 + wr) * ND + (kt)]       \
                                       : &Wl[(size_t)(n0 + wr) * ND + (kt)];      \
          uint32_t xh = smem_u32(&st[MM_XH + tid * MMST]);                        \
          uint32_t xl = smem_u32(&st[MM_XL + tid * MMST]);                        \
          uint32_t wb = smem_u32(&st[((tid < 64) ? MM_WH : MM_WL) + wr * MMST]);  \
          _Pragma("unroll") for (int g = 0; g < 4; g++) {                         \
              cp16(xh + g * 16, gxh + g * 8);                                     \
              cp16(xl + g * 16, gxl + g * 8);                                     \
              cp16(wb + g * 16, gw + g * 8);                                      \
          }                                                                       \
          CP_COMMIT(); }

    float acc[2][8][4] = {};
    MM_LOAD(0, 0);
    int s = 0;
    for (int kt = 0; kt < ND; kt += 32) {
        if (kt + 32 < ND) { MM_LOAD(kt + 32, s ^ 1); CP_WAIT1(); }
        else              { CP_WAIT0(); }
        __syncthreads();
        bf16* st = mms + s * MM_STAGE;
        #pragma unroll
        for (int kk = 0; kk < 32; kk += 16) {
            uint32_t Ah[2][4], Al[2][4];
            int arow = warp * 32 + (lane & 7) + ((lane >> 3) & 1) * 8;
            int acol = kk + (lane >> 4) * 8;
            ldsm4(Ah[0], smem_u32(&st[MM_XH + arow * MMST + acol]));
            ldsm4(Ah[1], smem_u32(&st[MM_XH + (arow + 16) * MMST + acol]));
            ldsm4(Al[0], smem_u32(&st[MM_XL + arow * MMST + acol]));
            ldsm4(Al[1], smem_u32(&st[MM_XL + (arow + 16) * MMST + acol]));
            #pragma unroll
            for (int nt2 = 0; nt2 < 4; nt2++) {
                uint32_t Bh[4], Bl[4];
                int brow = nt2 * 16 + (lane >> 4) * 8 + (lane & 7);
                int bcol = kk + ((lane >> 3) & 1) * 8;
                ldsm4(Bh, smem_u32(&st[MM_WH + brow * MMST + bcol]));
                ldsm4(Bl, smem_u32(&st[MM_WL + brow * MMST + bcol]));
                #pragma unroll
                for (int mt = 0; mt < 2; mt++)
                    #pragma unroll
                    for (int p = 0; p < 2; p++) {
                        mma16816(acc[mt][nt2 * 2 + p], Ah[mt], &Bh[p * 2]);
                        mma16816(acc[mt][nt2 * 2 + p], Ah[mt], &Bl[p * 2]);
                        mma16816(acc[mt][nt2 * 2 + p], Al[mt], &Bh[p * 2]);
                    }
            }
        }
        __syncthreads();
        s ^= 1;
    }

    const int r0 = lane >> 2, cc = (lane & 3) * 2;
    #pragma unroll
    for (int mt = 0; mt < 2; mt++)
        #pragma unroll
        for (int nt = 0; nt < 8; nt++) {
            int m = m0 + warp * 32 + mt * 16 + r0;
            int n = n0 + nt * 8 + cc;
            float b0 = bias[n], b1 = bias[n + 1];
            float v0 = acc[mt][nt][0] + b0, v1 = acc[mt][nt][1] + b1;
            float v2 = acc[mt][nt][2] + b0, v3 = acc[mt][nt][3] + b1;
            if (Yf) {
                *(float2*)&Yf[(size_t)m * ND + n]       = float2{v0, v1};
                *(float2*)&Yf[(size_t)(m + 8) * ND + n] = float2{v2, v3};
            }
            if (Yh) {
                bf16 h0 = __float2bfloat16_rn(v0), h1 = __float2bfloat16_rn(v1);
                bf16 h2 = __float2bfloat16_rn(v2), h3 = __float2bfloat16_rn(v3);
                *(bf162*)&Yh[(size_t)m * ND + n]       = bf162{h0, h1};
                *(bf162*)&Yh[(size_t)(m + 8) * ND + n] = bf162{h2, h3};
                *(bf162*)&Yl[(size_t)m * ND + n] =
                    bf162{__float2bfloat16_rn(v0 - __bfloat162float(h0)),
                          __float2bfloat16_rn(v1 - __bfloat162float(h1))};
                *(bf162*)&Yl[(size_t)(m + 8) * ND + n] =
                    bf162{__float2bfloat16_rn(v2 - __bfloat162float(h2)),
                          __float2bfloat16_rn(v3 - __bfloat162float(h3))};
            }
        }
}

// ---------------- logits = 0.125 * Q K^T (per head) -------------------------
#define QKS 72
#define QK_QH 0
#define QK_QL (QK_QH + 128 * QKS * 2)
#define QK_KH (QK_QL + 128 * QKS * 2)
#define QK_KL (QK_KH + 128 * QKS * 2)
#define QK_SMEM (QK_KL + 128 * QKS * 2)

__global__ __launch_bounds__(256) void qk_kernel()
{
    extern __shared__ char sm[];
    bf16* Qsh = (bf16*)(sm + QK_QH);
    bf16* Qsl = (bf16*)(sm + QK_QL);
    bf16* Ksh = (bf16*)(sm + QK_KH);
    bf16* Ksl = (bf16*)(sm + QK_KL);

    const int tid = threadIdx.x, lane = tid & 31, warp = tid >> 5;
    const int wm = warp & 3, wn = warp >> 2;
    const int h = blockIdx.z;
    const int q0 = blockIdx.y * 128, k0 = blockIdx.x * 128;
    const int ho = h * DH;

    const int lr = tid >> 2, lc = (tid & 3) * 16;
    #pragma unroll
    for (int it = 0; it < 2; it++) {
        int r = lr + it * 64;
        *(uint4*)&Qsh[r * QKS + lc]     = *(const uint4*)&g_Qh[(size_t)(q0 + r) * ND + ho + lc];
        *(uint4*)&Qsh[r * QKS + lc + 8] = *(const uint4*)&g_Qh[(size_t)(q0 + r) * ND + ho + lc + 8];
        *(uint4*)&Qsl[r * QKS + lc]     = *(const uint4*)&g_Ql[(size_t)(q0 + r) * ND + ho + lc];
        *(uint4*)&Qsl[r * QKS + lc + 8] = *(const uint4*)&g_Ql[(size_t)(q0 + r) * ND + ho + lc + 8];
        *(uint4*)&Ksh[r * QKS + lc]     = *(const uint4*)&g_Kh[(size_t)(k0 + r) * ND + ho + lc];
        *(uint4*)&Ksh[r * QKS + lc + 8] = *(const uint4*)&g_Kh[(size_t)(k0 + r) * ND + ho + lc + 8];
        *(uint4*)&Ksl[r * QKS + lc]     = *(const uint4*)&g_Kl[(size_t)(k0 + r) * ND + ho + lc];
        *(uint4*)&Ksl[r * QKS + lc + 8] = *(const uint4*)&g_Kl[(size_t)(k0 + r) * ND + ho + lc + 8];
    }
    __syncthreads();

    float acc[2][8][4] = {};
    #pragma unroll
    for (int kk = 0; kk < 64; kk += 16) {
        uint32_t Ah[2][4], Al[2][4];
        int arow = wm * 32 + (lane & 7) + ((lane >> 3) & 1) * 8;
        int acol = kk + (lane >> 4) * 8;
        ldsm4(Ah[0], smem_u32(&Qsh[arow * QKS + acol]));
        ldsm4(Ah[1], smem_u32(&Qsh[(arow + 16) * QKS + acol]));
        ldsm4(Al[0], smem_u32(&Qsl[arow * QKS + acol]));
        ldsm4(Al[1], smem_u32(&Qsl[(arow + 16) * QKS + acol]));
        #pragma unroll
        for (int nt2 = 0; nt2 < 4; nt2++) {
            uint32_t Bh[4], Bl[4];
            int brow = wn * 64 + nt2 * 16 + (lane >> 4) * 8 + (lane & 7);
            int bcol = kk + ((lane >> 3) & 1) * 8;
            ldsm4(Bh, smem_u32(&Ksh[brow * QKS + bcol]));
            ldsm4(Bl, smem_u32(&Ksl[brow * QKS + bcol]));
            #pragma unroll
            for (int mt = 0; mt < 2; mt++)
                #pragma unroll
                for (int p = 0; p < 2; p++) {
                    mma16816(acc[mt][nt2 * 2 + p], Ah[mt], &Bh[p * 2]);
                    mma16816(acc[mt][nt2 * 2 + p], Ah[mt], &Bl[p * 2]);
                    mma16816(acc[mt][nt2 * 2 + p], Al[mt], &Bh[p * 2]);
                }
        }
    }

    float* out = g_logits + (size_t)h * SEQ * SEQ;
    const int r0 = lane >> 2, cc = (lane & 3) * 2;
    #pragma unroll
    for (int mt = 0; mt < 2; mt++)
        #pragma unroll
        for (int nt = 0; nt < 8; nt++) {
            int m = q0 + wm * 32 + mt * 16 + r0;
            int n = k0 + wn * 64 + nt * 8 + cc;
            *(float2*)&out[(size_t)m * SEQ + n] =
                float2{acc[mt][nt][0] * 0.125f, acc[mt][nt][1] * 0.125f};
            *(float2*)&out[(size_t)(m + 8) * SEQ + n] =
                float2{acc[mt][nt][2] * 0.125f, acc[mt][nt][3] * 0.125f};
        }
}

// -------- li[h,q,n] = sum_d Q[q, h*64+d] * pos_emb[d, n] --------------------
__global__ __launch_bounds__(256) void li_kernel(const float* __restrict__ pos_emb)
{
    __shared__ float Qs[64][65];
    __shared__ float Ps[64][65];
    const int tid = threadIdx.x;
    const int tx = tid & 15, ty = tid >> 4;
    const int h = blockIdx.y;
    const int q0 = blockIdx.x * 64;

    for (int i = tid; i < 64 * 64; i += 256) {
        int r = i >> 6, c = i & 63;
        Qs[r][c] = g_Q[(q0 + r) * ND + h * DH + c];
        Ps[r][c] = pos_emb[r * NPOS + c];
    }
    __syncthreads();

    float acc[4][4] = {};
    #pragma unroll 8
    for (int d = 0; d < 64; d++) {
        float a[4], b[4];
        #pragma unroll
        for (int i = 0; i < 4; i++) a[i] = Qs[ty * 4 + i][d];
        #pragma unroll
        for (int j = 0; j < 4; j++) b[j] = Ps[d][tx * 4 + j];
        #pragma unroll
        for (int i = 0; i < 4; i++)
            #pragma unroll
            for (int j = 0; j < 4; j++) acc[i][j] += a[i] * b[j];
    }
    #pragma unroll
    for (int i = 0; i < 4; i++)
        #pragma unroll
        for (int j = 0; j < 4; j++)
            g_li[(h * SEQ + q0 + ty * 4 + i) * NPOS + tx * 4 + j] = acc[i][j];
}

// -------- per (h,q) row: gates -> suffix-cumsum -> CoPE -> softmax ----------
__global__ __launch_bounds__(256) void cope_softmax_kernel()
{
    __shared__ float li[NPOS];
    __shared__ float wsum[8];
    __shared__ float redm[8];
    __shared__ float reds[8];

    const int tid = threadIdx.x;
    const int lane = tid & 31, warp = tid >> 5;
    const int q = blockIdx.x, h = blockIdx.y;
    const size_t rbase = ((size_t)h * SEQ + q) * SEQ;
    const float* lrow = g_logits + rbase;

    if (tid < NPOS) li[tid] = g_li[(h * SEQ + q) * NPOS + tid];

    const int base = tid * 8;
    float x[8];
    *(float4*)&x[0] = *(const float4*)&lrow[base];
    *(float4*)&x[4] = *(const float4*)&lrow[base + 4];

    float g[8];
    float csum = 0.0f;
    #pragma unroll
    for (int j = 7; j >= 0; --j) {
        float t;
        asm("tanh.approx.f32 %0, %1;" : "=f"(t) : "f"(x[j] * 0.5f));
        csum += fmaf(t, 0.5f, 0.5f);
        g[j] = csum;
    }
    float v = csum;
    #pragma unroll
    for (int d = 1; d < 32; d <<= 1) {
        float n = __shfl_up_sync(0xffffffffu, v, d);
        if (lane >= d) v += n;
    }
    if (lane == 31) wsum[warp] = v;
    __syncthreads();
    float wpre = 0.0f, total = 0.0f;
    #pragma unroll
    for (int w = 0; w < 8; w++) {
        float s = wsum[w];
        if (w < warp) wpre += s;
        total += s;
    }
    const float off = total - (wpre + v);

    float lmax = -INFINITY;
    #pragma unroll
    for (int j = 0; j < 8; j++) {
        float pos = fminf(g[j] + off, (float)(NPOS - 1));
        float pf = floorf(pos);
        int fi = (int)pf;
        int ci = (int)ceilf(pos);
        float w = pos - pf;
        x[j] += li[ci] * w + li[fi] * (1.0f - w);
        lmax = fmaxf(lmax, x[j]);
    }
    #pragma unroll
    for (int d = 16; d > 0; d >>= 1)
        lmax = fmaxf(lmax, __shfl_xor_sync(0xffffffffu, lmax, d));
    if (lane == 0) redm[warp] = lmax;
    __syncthreads();
    float mx = redm[0];
    #pragma unroll
    for (int w = 1; w < 8; w++) mx = fmaxf(mx, redm[w]);

    float lsum = 0.0f;
    #pragma unroll
    for (int j = 0; j < 8; j++) {
        x[j] = __expf(x[j] - mx);
        lsum += x[j];
    }
    #pragma unroll
    for (int d = 16; d > 0; d >>= 1)
        lsum += __shfl_xor_sync(0xffffffffu, lsum, d);
    if (lane == 0) reds[warp] = lsum;
    __syncthreads();
    float tsum = 0.0f;
    #pragma unroll
    for (int w = 0; w < 8; w++) tsum += reds[w];
    const float inv = 1.0f / tsum;

    bf16* sh = g_Sh + rbase + base;
    bf16* sl = g_Sl + rbase + base;
    #pragma unroll
    for (int jp = 0; jp < 4; jp++) {
        float a = x[2 * jp] * inv, b = x[2 * jp + 1] * inv;
        bf16 ha = __float2bfloat16_rn(a), hb = __float2bfloat16_rn(b);
        ((bf162*)sh)[jp] = bf162{ha, hb};
        ((bf162*)sl)[jp] = bf162{__float2bfloat16_rn(a - __bfloat162float(ha)),
                                 __float2bfloat16_rn(b - __bfloat162float(hb))};
    }
}

// -------- ctx = scores @ V (split-bf16, cp.async 2-stage) -------------------
// Block 128(q) x 64(n=head), BK=32, 4 warps (warp tile 32x64). 3 CTAs/SM.
#define CXST  40
#define CXVST 72
#define CX_SH 0
#define CX_SL (128 * CXST)
#define CX_VH (256 * CXST)
#define CX_VL (256 * CXST + 32 * CXVST)
#define CX_STAGE (256 * CXST + 64 * CXVST)   // elems
#define CX_SMEM  (2 * CX_STAGE * 2)          // 59392 bytes

__global__ __launch_bounds__(128, 3) void ctx_kernel()
{
    extern __shared__ bf16 cxs[];
    const int tid = threadIdx.x, lane = tid & 31, warp = tid >> 5;
    const int h = blockIdx.y;
    const int q0 = blockIdx.x * 128;
    const int ho = h * DH;
    const bf16* Sh = g_Sh + (size_t)h * SEQ * SEQ;
    const bf16* Sl = g_Sl + (size_t)h * SEQ * SEQ;

    const int vr = tid >> 2, vc = (tid & 3) * 16;   // V loader: 32 rows x 4 col-chunks

    #define CX_LOAD(kt, s)                                                        \
        { bf16* st = cxs + (s) * CX_STAGE;                                        \
          const bf16* gsh = &Sh[(size_t)(q0 + tid) * SEQ + (kt)];                 \
          const bf16* gsl = &Sl[(size_t)(q0 + tid) * SEQ + (kt)];                 \
          uint32_t ash = smem_u32(&st[CX_SH + tid * CXST]);                       \
          uint32_t asl = smem_u32(&st[CX_SL + tid * CXST]);                       \
          _Pragma("unroll") for (int g = 0; g < 4; g++) {                         \
              cp16(ash + g * 16, gsh + g * 8);                                    \
              cp16(asl + g * 16, gsl + g * 8);                                    \
          }                                                                       \
          uint32_t avh = smem_u32(&st[CX_VH + vr * CXVST + vc]);                  \
          uint32_t avl = smem_u32(&st[CX_VL + vr * CXVST + vc]);                  \
          const bf16* gvh = &g_Vh[(size_t)((kt) + vr) * ND + ho + vc];            \
          const bf16* gvl = &g_Vl[(size_t)((kt) + vr) * ND + ho + vc];            \
          cp16(avh, gvh); cp16(avh + 16, gvh + 8);                                \
          cp16(avl, gvl); cp16(avl + 16, gvl + 8);                                \
          CP_COMMIT(); }

    float acc[2][8][4] = {};
    CX_LOAD(0, 0);
    int s = 0;
    for (int kt = 0; kt < SEQ; kt += 32) {
        if (kt + 32 < SEQ) { CX_LOAD(kt + 32, s ^ 1); CP_WAIT1(); }
        else               { CP_WAIT0(); }
        __syncthreads();
        bf16* st = cxs + s * CX_STAGE;
        #pragma unroll
        for (int kk = 0; kk < 32; kk += 16) {
            uint32_t Ah[2][4], Al[2][4];
            int arow = warp * 32 + (lane & 7) + ((lane >> 3) & 1) * 8;
            int acol = kk + (lane >> 4) * 8;
            ldsm4(Ah[0], smem_u32(&st[CX_SH + arow * CXST + acol]));
            ldsm4(Ah[1], smem_u32(&st[CX_SH + (arow + 16) * CXST + acol]));
            ldsm4(Al[0], smem_u32(&st[CX_SL + arow * CXST + acol]));
            ldsm4(Al[1], smem_u32(&st[CX_SL + (arow + 16) * CXST + acol]));
            #pragma unroll
            for (int nt2 = 0; nt2 < 4; nt2++) {
                uint32_t Bh[4], Bl[4];
                int vrow = kk + ((lane >> 3) & 1) * 8 + (lane & 7);
                int vcol = nt2 * 16 + (lane >> 4) * 8;
                ldsm4t(Bh, smem_u32(&st[CX_VH + vrow * CXVST + vcol]));
                ldsm4t(Bl, smem_u32(&st[CX_VL + vrow * CXVST + vcol]));
                #pragma unroll
                for (int mt = 0; mt < 2; mt++)
                    #pragma unroll
                    for (int p = 0; p < 2; p++) {
                        mma16816(acc[mt][nt2 * 2 + p], Ah[mt], &Bh[p * 2]);
                        mma16816(acc[mt][nt2 * 2 + p], Ah[mt], &Bl[p * 2]);
                        mma16816(acc[mt][nt2 * 2 + p], Al[mt], &Bh[p * 2]);
                    }
            }
        }
        __syncthreads();
        s ^= 1;
    }

    const int r0 = lane >> 2, cc = (lane & 3) * 2;
    #pragma unroll
    for (int mt = 0; mt < 2; mt++)
        #pragma unroll
        for (int nt = 0; nt < 8; nt++) {
            int m = q0 + warp * 32 + mt * 16 + r0;
            int n = ho + nt * 8 + cc;
            float v0 = acc[mt][nt][0], v1 = acc[mt][nt][1];
            float v2 = acc[mt][nt][2], v3 = acc[mt][nt][3];
            bf16 h0 = __float2bfloat16_rn(v0), h1 = __float2bfloat16_rn(v1);
            bf16 h2 = __float2bfloat16_rn(v2), h3 = __float2bfloat16_rn(v3);
            *(bf162*)&g_ctxh[(size_t)m * ND + n]       = bf162{h0, h1};
            *(bf162*)&g_ctxh[(size_t)(m + 8) * ND + n] = bf162{h2, h3};
            *(bf162*)&g_ctxl[(size_t)m * ND + n] =
                bf162{__float2bfloat16_rn(v0 - __bfloat162float(h0)),
                      __float2bfloat16_rn(v1 - __bfloat162float(h1))};
            *(bf162*)&g_ctxl[(size_t)(m + 8) * ND + n] =
                bf162{__float2bfloat16_rn(v2 - __bfloat162float(h2)),
                      __float2bfloat16_rn(v3 - __bfloat162float(h3))};
        }
}

// ---------------------------------------------------------------------------
extern "C" void kernel_launch(void* const* d_in, const int* in_sizes, int n_in,
                              void* d_out, int out_size)
{
    const float* q      = (const float*)d_in[0];
    const float* k      = (const float*)d_in[1];
    const float* v      = (const float*)d_in[2];
    const float* Wq_w   = (const float*)d_in[3];
    const float* Wq_b   = (const float*)d_in[4];
    const float* Wk_w   = (const float*)d_in[5];
    const float* Wk_b   = (const float*)d_in[6];
    const float* Wv_w   = (const float*)d_in[7];
    const float* Wv_b   = (const float*)d_in[8];
    const float* Wo_w   = (const float*)d_in[9];
    const float* Wo_b   = (const float*)d_in[10];
    const float* pos_emb= (const float*)d_in[11];
    float* out = (float*)d_out;

    static bool attr_set = false;
    if (!attr_set) {
        cudaFuncSetAttribute(mm_bias_kernel,
                             cudaFuncAttributeMaxDynamicSharedMemorySize, MM_SMEM);
        cudaFuncSetAttribute(qk_kernel,
                             cudaFuncAttributeMaxDynamicSharedMemorySize, QK_SMEM);
        cudaFuncSetAttribute(ctx_kernel,
                             cudaFuncAttributeMaxDynamicSharedMemorySize, CX_SMEM);
        attr_set = true;
    }

    bf16 *inqh, *inql, *inkh, *inkl, *invh, *invl;
    bf16 *wqh, *wql, *wkh, *wkl, *wvh, *wvl, *woh, *wol;
    bf16 *Qh, *Ql, *Kh, *Kl, *Vh, *Vl, *ctxh, *ctxl;
    float* Qf;
    cudaGetSymbolAddress((void**)&inqh, g_inqh); cudaGetSymbolAddress((void**)&inql, g_inql);
    cudaGetSymbolAddress((void**)&inkh, g_inkh); cudaGetSymbolAddress((void**)&inkl, g_inkl);
    cudaGetSymbolAddress((void**)&invh, g_invh); cudaGetSymbolAddress((void**)&invl, g_invl);
    cudaGetSymbolAddress((void**)&wqh, g_wqh);   cudaGetSymbolAddress((void**)&wql, g_wql);
    cudaGetSymbolAddress((void**)&wkh, g_wkh);   cudaGetSymbolAddress((void**)&wkl, g_wkl);
    cudaGetSymbolAddress((void**)&wvh, g_wvh);   cudaGetSymbolAddress((void**)&wvl, g_wvl);
    cudaGetSymbolAddress((void**)&woh, g_woh);   cudaGetSymbolAddress((void**)&wol, g_wol);
    cudaGetSymbolAddress((void**)&Qh, g_Qh);     cudaGetSymbolAddress((void**)&Ql, g_Ql);
    cudaGetSymbolAddress((void**)&Kh, g_Kh);     cudaGetSymbolAddress((void**)&Kl, g_Kl);
    cudaGetSymbolAddress((void**)&Vh, g_Vh);     cudaGetSymbolAddress((void**)&Vl, g_Vl);
    cudaGetSymbolAddress((void**)&ctxh, g_ctxh); cudaGetSymbolAddress((void**)&ctxl, g_ctxl);
    cudaGetSymbolAddress((void**)&Qf, g_Q);

    const int nIn = SEQ * ND / 1024;
    const int nW  = ND * ND / 1024;

    split3_kernel<<<dim3(nIn, 3), 256>>>(q, k, v,
                                         inqh, inql, inkh, inkl, invh, invl);
    split4_kernel<<<dim3(nW, 4), 256>>>(Wq_w, Wk_w, Wv_w, Wo_w,
                                        wqh, wql, wkh, wkl, wvh, wvl, woh, wol);

    dim3 gProj(ND / 64, SEQ / 128);   // (16, 16) = 256 CTAs
    mm_bias_kernel<<<gProj, 128, MM_SMEM>>>(inqh, inql, wqh, wql, Wq_b, Qf, Qh, Ql);
    mm_bias_kernel<<<gProj, 128, MM_SMEM>>>(inkh, inkl, wkh, wkl, Wk_b, nullptr, Kh, Kl);
    mm_bias_kernel<<<gProj, 128, MM_SMEM>>>(invh, invl, wvh, wvl, Wv_b, nullptr, Vh, Vl);

    qk_kernel<<<dim3(SEQ / 128, SEQ / 128, NH), 256, QK_SMEM>>>();
    li_kernel<<<dim3(SEQ / 64, NH), 256>>>(pos_emb);
    cope_softmax_kernel<<<dim3(SEQ, NH), 256>>>();
    ctx_kernel<<<dim3(SEQ / 128, NH), 128, CX_SMEM>>>();

    mm_bias_kernel<<<gProj, 128, MM_SMEM>>>(ctxh, ctxl, woh, wol, Wo_b, out, nullptr, nullptr);
}

// round 14
// speedup vs baseline: 1.2536x; 1.2536x over previous
#include <cuda_runtime.h>
#include <cuda_bf16.h>
#include <math.h>
#include <stdint.h>

#define SEQ   2048
#define ND    1024
#define NH    16
#define DH    64
#define NPOS  64

typedef __nv_bfloat16 bf16;
typedef __nv_bfloat162 bf162;

// ---------------- scratch (device globals: allocation-free) ----------------
__device__ float g_Q[SEQ * ND];
__device__ float g_logits[(size_t)NH * SEQ * SEQ];    // 256 MB fp32 logits
__device__ float g_li[NH * SEQ * NPOS];

__device__ bf16 g_inqh[SEQ * ND], g_inql[SEQ * ND];
__device__ bf16 g_inkh[SEQ * ND], g_inkl[SEQ * ND];
__device__ bf16 g_invh[SEQ * ND], g_invl[SEQ * ND];
__device__ bf16 g_wqh[ND * ND], g_wql[ND * ND];
__device__ bf16 g_wkh[ND * ND], g_wkl[ND * ND];
__device__ bf16 g_wvh[ND * ND], g_wvl[ND * ND];
__device__ bf16 g_woh[ND * ND], g_wol[ND * ND];
__device__ bf16 g_Qh[SEQ * ND], g_Ql[SEQ * ND];
__device__ bf16 g_Kh[SEQ * ND], g_Kl[SEQ * ND];
__device__ bf16 g_Vh[SEQ * ND], g_Vl[SEQ * ND];
__device__ bf16 g_ctxh[SEQ * ND], g_ctxl[SEQ * ND];
__device__ bf16 g_Sh[(size_t)NH * SEQ * SEQ];
__device__ bf16 g_Sl[(size_t)NH * SEQ * SEQ];

// ---------------- PTX helpers ----------------------------------------------
__device__ __forceinline__ uint32_t smem_u32(const void* p) {
    return (uint32_t)__cvta_generic_to_shared(p);
}
__device__ __forceinline__ void ldsm4(uint32_t* r, uint32_t a) {
    asm volatile("ldmatrix.sync.aligned.m8n8.x4.shared.b16 {%0,%1,%2,%3}, [%4];"
                 : "=r"(r[0]), "=r"(r[1]), "=r"(r[2]), "=r"(r[3]) : "r"(a));
}
__device__ __forceinline__ void ldsm4t(uint32_t* r, uint32_t a) {
    asm volatile("ldmatrix.sync.aligned.m8n8.x4.trans.shared.b16 {%0,%1,%2,%3}, [%4];"
                 : "=r"(r[0]), "=r"(r[1]), "=r"(r[2]), "=r"(r[3]) : "r"(a));
}
__device__ __forceinline__ void mma16816(float* c, const uint32_t* a, const uint32_t* b) {
    asm volatile(
        "mma.sync.aligned.m16n8k16.row.col.f32.bf16.bf16.f32 "
        "{%0,%1,%2,%3}, {%4,%5,%6,%7}, {%8,%9}, {%0,%1,%2,%3};"
        : "+f"(c[0]), "+f"(c[1]), "+f"(c[2]), "+f"(c[3])
        : "r"(a[0]), "r"(a[1]), "r"(a[2]), "r"(a[3]), "r"(b[0]), "r"(b[1]));
}
__device__ __forceinline__ void cp16(uint32_t sa, const void* g) {
    asm volatile("cp.async.cg.shared.global [%0], [%1], 16;" :: "r"(sa), "l"(g));
}
#define CP_COMMIT() asm volatile("cp.async.commit_group;" ::: "memory")
#define CP_WAIT2()  asm volatile("cp.async.wait_group 2;" ::: "memory")
#define CP_WAIT1()  asm volatile("cp.async.wait_group 1;" ::: "memory")
#define CP_WAIT0()  asm volatile("cp.async.wait_group 0;" ::: "memory")

// ---------------- split fp32 -> bf16 hi + bf16 lo (batched) -----------------
__device__ __forceinline__ void split_body(const float* __restrict__ s,
                                           bf16* __restrict__ hi, bf16* __restrict__ lo)
{
    int i = (blockIdx.x * 256 + threadIdx.x) * 4;
    float4 v = *(const float4*)&s[i];
    bf16 h0 = __float2bfloat16_rn(v.x), h1 = __float2bfloat16_rn(v.y);
    bf16 h2 = __float2bfloat16_rn(v.z), h3 = __float2bfloat16_rn(v.w);
    bf16 l0 = __float2bfloat16_rn(v.x - __bfloat162float(h0));
    bf16 l1 = __float2bfloat16_rn(v.y - __bfloat162float(h1));
    bf16 l2 = __float2bfloat16_rn(v.z - __bfloat162float(h2));
    bf16 l3 = __float2bfloat16_rn(v.w - __bfloat162float(h3));
    *(bf162*)&hi[i]     = bf162{h0, h1};
    *(bf162*)&hi[i + 2] = bf162{h2, h3};
    *(bf162*)&lo[i]     = bf162{l0, l1};
    *(bf162*)&lo[i + 2] = bf162{l2, l3};
}

__global__ __launch_bounds__(256) void split3_kernel(
    const float* s0, const float* s1, const float* s2,
    bf16* h0, bf16* l0, bf16* h1, bf16* l1, bf16* h2, bf16* l2)
{
    const float* s = (blockIdx.y == 0) ? s0 : (blockIdx.y == 1) ? s1 : s2;
    bf16* hp = (blockIdx.y == 0) ? h0 : (blockIdx.y == 1) ? h1 : h2;
    bf16* lp = (blockIdx.y == 0) ? l0 : (blockIdx.y == 1) ? l1 : l2;
    split_body(s, hp, lp);
}

__global__ __launch_bounds__(256) void split4_kernel(
    const float* s0, const float* s1, const float* s2, const float* s3,
    bf16* h0, bf16* l0, bf16* h1, bf16* l1,
    bf16* h2, bf16* l2, bf16* h3, bf16* l3)
{
    const float* s = (blockIdx.y == 0) ? s0 : (blockIdx.y == 1) ? s1 :
                     (blockIdx.y == 2) ? s2 : s3;
    bf16* hp = (blockIdx.y == 0) ? h0 : (blockIdx.y == 1) ? h1 :
               (blockIdx.y == 2) ? h2 : h3;
    bf16* lp = (blockIdx.y == 0) ? l0 : (blockIdx.y == 1) ? l1 :
               (blockIdx.y == 2) ? l2 : l3;
    split_body(s, hp, lp);
}

// ---------------- Y = X @ W^T + bias (split-bf16, cp.async 3-stage) ---------
// Block 128(m) x 64(n), BK=32, 8 warps (warp tile 32x32). 2 CTAs/SM.
// Batched over blockIdx.z (up to 3 independent GEMMs per launch).
struct MMJob {
    const bf16 *Xh, *Xl, *Wh, *Wl;
    const float* bias;
    float* Yf;
    bf16 *Yh, *Yl;
};

#define MMST 40
#define MM_XH 0
#define MM_XL (128 * MMST)
#define MM_WH (256 * MMST)
#define MM_WL (320 * MMST)
#define MM_STAGE (384 * MMST)            // elems per stage (30720 B)
#define MM_SMEM  (3 * MM_STAGE * 2)      // 92160 bytes

__global__ __launch_bounds__(256, 2) void mm_bias_kernel(MMJob j0, MMJob j1, MMJob j2)
{
    extern __shared__ bf16 mms[];
    const MMJob j = (blockIdx.z == 0) ? j0 : (blockIdx.z == 1) ? j1 : j2;
    const bf16* __restrict__ Xh = j.Xh;
    const bf16* __restrict__ Xl = j.Xl;
    const bf16* __restrict__ Wh = j.Wh;
    const bf16* __restrict__ Wl = j.Wl;

    const int tid = threadIdx.x, lane = tid & 31, warp = tid >> 5;
    const int wm = warp & 3, wn = warp >> 2;
    const int m0 = blockIdx.y * 128, n0 = blockIdx.x * 64;
    const int xr = tid >> 2, xc = (tid & 3) * 8;

    #define MM_LOAD(kt, s)                                                        \
        { bf16* st = mms + (s) * MM_STAGE;                                        \
          cp16(smem_u32(&st[MM_XH + xr * MMST + xc]),                             \
               &Xh[(size_t)(m0 + xr) * ND + (kt) + xc]);                          \
          cp16(smem_u32(&st[MM_XH + (xr + 64) * MMST + xc]),                      \
               &Xh[(size_t)(m0 + xr + 64) * ND + (kt) + xc]);                     \
          cp16(smem_u32(&st[MM_XL + xr * MMST + xc]),                             \
               &Xl[(size_t)(m0 + xr) * ND + (kt) + xc]);                          \
          cp16(smem_u32(&st[MM_XL + (xr + 64) * MMST + xc]),                      \
               &Xl[(size_t)(m0 + xr + 64) * ND + (kt) + xc]);                     \
          cp16(smem_u32(&st[MM_WH + xr * MMST + xc]),                             \
               &Wh[(size_t)(n0 + xr) * ND + (kt) + xc]);                          \
          cp16(smem_u32(&st[MM_WL + xr * MMST + xc]),                             \
               &Wl[(size_t)(n0 + xr) * ND + (kt) + xc]);                          \
          CP_COMMIT(); }

    float acc[2][4][4] = {};
    MM_LOAD(0, 0);
    MM_LOAD(32, 1);
    int s = 0;
    for (int kt = 0; kt < ND; kt += 32) {
        if (kt + 64 < ND) {
            int sn = s + 2; if (sn >= 3) sn -= 3;
            MM_LOAD(kt + 64, sn);
            CP_WAIT2();
        } else if (kt + 32 < ND) {
            CP_WAIT1();
        } else {
            CP_WAIT0();
        }
        __syncthreads();
        bf16* st = mms + s * MM_STAGE;
        #pragma unroll
        for (int kk = 0; kk < 32; kk += 16) {
            uint32_t Ah[2][4], Al[2][4];
            int arow = wm * 32 + (lane & 7) + ((lane >> 3) & 1) * 8;
            int acol = kk + (lane >> 4) * 8;
            ldsm4(Ah[0], smem_u32(&st[MM_XH + arow * MMST + acol]));
            ldsm4(Ah[1], smem_u32(&st[MM_XH + (arow + 16) * MMST + acol]));
            ldsm4(Al[0], smem_u32(&st[MM_XL + arow * MMST + acol]));
            ldsm4(Al[1], smem_u32(&st[MM_XL + (arow + 16) * MMST + acol]));
            #pragma unroll
            for (int nt2 = 0; nt2 < 2; nt2++) {
                uint32_t Bh[4], Bl[4];
                int brow = wn * 32 + nt2 * 16 + (lane >> 4) * 8 + (lane & 7);
                int bcol = kk + ((lane >> 3) & 1) * 8;
                ldsm4(Bh, smem_u32(&st[MM_WH + brow * MMST + bcol]));
                ldsm4(Bl, smem_u32(&st[MM_WL + brow * MMST + bcol]));
                #pragma unroll
                for (int mt = 0; mt < 2; mt++)
                    #pragma unroll
                    for (int p = 0; p < 2; p++) {
                        mma16816(acc[mt][nt2 * 2 + p], Ah[mt], &Bh[p * 2]);
                        mma16816(acc[mt][nt2 * 2 + p], Ah[mt], &Bl[p * 2]);
                        mma16816(acc[mt][nt2 * 2 + p], Al[mt], &Bh[p * 2]);
                    }
            }
        }
        __syncthreads();
        s = (s + 1 >= 3) ? 0 : s + 1;
    }

    const int r0 = lane >> 2, cc = (lane & 3) * 2;
    #pragma unroll
    for (int mt = 0; mt < 2; mt++)
        #pragma unroll
        for (int nt = 0; nt < 4; nt++) {
            int m = m0 + wm * 32 + mt * 16 + r0;
            int n = n0 + wn * 32 + nt * 8 + cc;
            float b0 = j.bias[n], b1 = j.bias[n + 1];
            float v0 = acc[mt][nt][0] + b0, v1 = acc[mt][nt][1] + b1;
            float v2 = acc[mt][nt][2] + b0, v3 = acc[mt][nt][3] + b1;
            if (j.Yf) {
                *(float2*)&j.Yf[(size_t)m * ND + n]       = float2{v0, v1};
                *(float2*)&j.Yf[(size_t)(m + 8) * ND + n] = float2{v2, v3};
            }
            if (j.Yh) {
                bf16 h0 = __float2bfloat16_rn(v0), h1 = __float2bfloat16_rn(v1);
                bf16 h2 = __float2bfloat16_rn(v2), h3 = __float2bfloat16_rn(v3);
                *(bf162*)&j.Yh[(size_t)m * ND + n]       = bf162{h0, h1};
                *(bf162*)&j.Yh[(size_t)(m + 8) * ND + n] = bf162{h2, h3};
                *(bf162*)&j.Yl[(size_t)m * ND + n] =
                    bf162{__float2bfloat16_rn(v0 - __bfloat162float(h0)),
                          __float2bfloat16_rn(v1 - __bfloat162float(h1))};
                *(bf162*)&j.Yl[(size_t)(m + 8) * ND + n] =
                    bf162{__float2bfloat16_rn(v2 - __bfloat162float(h2)),
                          __float2bfloat16_rn(v3 - __bfloat162float(h3))};
            }
        }
}

// ---------------- logits = 0.125 * Q K^T (per head) -------------------------
#define QKS 72
#define QK_QH 0
#define QK_QL (QK_QH + 128 * QKS * 2)
#define QK_KH (QK_QL + 128 * QKS * 2)
#define QK_KL (QK_KH + 128 * QKS * 2)
#define QK_SMEM (QK_KL + 128 * QKS * 2)

__global__ __launch_bounds__(256) void qk_kernel()
{
    extern __shared__ char sm[];
    bf16* Qsh = (bf16*)(sm + QK_QH);
    bf16* Qsl = (bf16*)(sm + QK_QL);
    bf16* Ksh = (bf16*)(sm + QK_KH);
    bf16* Ksl = (bf16*)(sm + QK_KL);

    const int tid = threadIdx.x, lane = tid & 31, warp = tid >> 5;
    const int wm = warp & 3, wn = warp >> 2;
    const int h = blockIdx.z;
    const int q0 = blockIdx.y * 128, k0 = blockIdx.x * 128;
    const int ho = h * DH;

    const int lr = tid >> 2, lc = (tid & 3) * 16;
    #pragma unroll
    for (int it = 0; it < 2; it++) {
        int r = lr + it * 64;
        *(uint4*)&Qsh[r * QKS + lc]     = *(const uint4*)&g_Qh[(size_t)(q0 + r) * ND + ho + lc];
        *(uint4*)&Qsh[r * QKS + lc + 8] = *(const uint4*)&g_Qh[(size_t)(q0 + r) * ND + ho + lc + 8];
        *(uint4*)&Qsl[r * QKS + lc]     = *(const uint4*)&g_Ql[(size_t)(q0 + r) * ND + ho + lc];
        *(uint4*)&Qsl[r * QKS + lc + 8] = *(const uint4*)&g_Ql[(size_t)(q0 + r) * ND + ho + lc + 8];
        *(uint4*)&Ksh[r * QKS + lc]     = *(const uint4*)&g_Kh[(size_t)(k0 + r) * ND + ho + lc];
        *(uint4*)&Ksh[r * QKS + lc + 8] = *(const uint4*)&g_Kh[(size_t)(k0 + r) * ND + ho + lc + 8];
        *(uint4*)&Ksl[r * QKS + lc]     = *(const uint4*)&g_Kl[(size_t)(k0 + r) * ND + ho + lc];
        *(uint4*)&Ksl[r * QKS + lc + 8] = *(const uint4*)&g_Kl[(size_t)(k0 + r) * ND + ho + lc + 8];
    }
    __syncthreads();

    float acc[2][8][4] = {};
    #pragma unroll
    for (int kk = 0; kk < 64; kk += 16) {
        uint32_t Ah[2][4], Al[2][4];
        int arow = wm * 32 + (lane & 7) + ((lane >> 3) & 1) * 8;
        int acol = kk + (lane >> 4) * 8;
        ldsm4(Ah[0], smem_u32(&Qsh[arow * QKS + acol]));
        ldsm4(Ah[1], smem_u32(&Qsh[(arow + 16) * QKS + acol]));
        ldsm4(Al[0], smem_u32(&Qsl[arow * QKS + acol]));
        ldsm4(Al[1], smem_u32(&Qsl[(arow + 16) * QKS + acol]));
        #pragma unroll
        for (int nt2 = 0; nt2 < 4; nt2++) {
            uint32_t Bh[4], Bl[4];
            int brow = wn * 64 + nt2 * 16 + (lane >> 4) * 8 + (lane & 7);
            int bcol = kk + ((lane >> 3) & 1) * 8;
            ldsm4(Bh, smem_u32(&Ksh[brow * QKS + bcol]));
            ldsm4(Bl, smem_u32(&Ksl[brow * QKS + bcol]));
            #pragma unroll
            for (int mt = 0; mt < 2; mt++)
                #pragma unroll
                for (int p = 0; p < 2; p++) {
                    mma16816(acc[mt][nt2 * 2 + p], Ah[mt], &Bh[p * 2]);
                    mma16816(acc[mt][nt2 * 2 + p], Ah[mt], &Bl[p * 2]);
                    mma16816(acc[mt][nt2 * 2 + p], Al[mt], &Bh[p * 2]);
                }
        }
    }

    float* out = g_logits + (size_t)h * SEQ * SEQ;
    const int r0 = lane >> 2, cc = (lane & 3) * 2;
    #pragma unroll
    for (int mt = 0; mt < 2; mt++)
        #pragma unroll
        for (int nt = 0; nt < 8; nt++) {
            int m = q0 + wm * 32 + mt * 16 + r0;
            int n = k0 + wn * 64 + nt * 8 + cc;
            *(float2*)&out[(size_t)m * SEQ + n] =
                float2{acc[mt][nt][0] * 0.125f, acc[mt][nt][1] * 0.125f};
            *(float2*)&out[(size_t)(m + 8) * SEQ + n] =
                float2{acc[mt][nt][2] * 0.125f, acc[mt][nt][3] * 0.125f};
        }
}

// -------- li[h,q,n] = sum_d Q[q, h*64+d] * pos_emb[d, n] --------------------
__global__ __launch_bounds__(256) void li_kernel(const float* __restrict__ pos_emb)
{
    __shared__ float Qs[64][65];
    __shared__ float Ps[64][65];
    const int tid = threadIdx.x;
    const int tx = tid & 15, ty = tid >> 4;
    const int h = blockIdx.y;
    const int q0 = blockIdx.x * 64;

    for (int i = tid; i < 64 * 64; i += 256) {
        int r = i >> 6, c = i & 63;
        Qs[r][c] = g_Q[(q0 + r) * ND + h * DH + c];
        Ps[r][c] = pos_emb[r * NPOS + c];
    }
    __syncthreads();

    float acc[4][4] = {};
    #pragma unroll 8
    for (int d = 0; d < 64; d++) {
        float a[4], b[4];
        #pragma unroll
        for (int i = 0; i < 4; i++) a[i] = Qs[ty * 4 + i][d];
        #pragma unroll
        for (int j = 0; j < 4; j++) b[j] = Ps[d][tx * 4 + j];
        #pragma unroll
        for (int i = 0; i < 4; i++)
            #pragma unroll
            for (int j = 0; j < 4; j++) acc[i][j] += a[i] * b[j];
    }
    #pragma unroll
    for (int i = 0; i < 4; i++)
        #pragma unroll
        for (int j = 0; j < 4; j++)
            g_li[(h * SEQ + q0 + ty * 4 + i) * NPOS + tx * 4 + j] = acc[i][j];
}

// -------- per (h,q) row: gates -> suffix-cumsum -> CoPE -> softmax ----------
__global__ __launch_bounds__(256) void cope_softmax_kernel()
{
    __shared__ float li[NPOS];
    __shared__ float wsum[8];
    __shared__ float redm[8];
    __shared__ float reds[8];

    const int tid = threadIdx.x;
    const int lane = tid & 31, warp = tid >> 5;
    const int q = blockIdx.x, h = blockIdx.y;
    const size_t rbase = ((size_t)h * SEQ + q) * SEQ;
    const float* lrow = g_logits + rbase;

    if (tid < NPOS) li[tid] = g_li[(h * SEQ + q) * NPOS + tid];

    const int base = tid * 8;
    float x[8];
    *(float4*)&x[0] = *(const float4*)&lrow[base];
    *(float4*)&x[4] = *(const float4*)&lrow[base + 4];

    float g[8];
    float csum = 0.0f;
    #pragma unroll
    for (int j = 7; j >= 0; --j) {
        float t;
        asm("tanh.approx.f32 %0, %1;" : "=f"(t) : "f"(x[j] * 0.5f));
        csum += fmaf(t, 0.5f, 0.5f);
        g[j] = csum;
    }
    float v = csum;
    #pragma unroll
    for (int d = 1; d < 32; d <<= 1) {
        float n = __shfl_up_sync(0xffffffffu, v, d);
        if (lane >= d) v += n;
    }
    if (lane == 31) wsum[warp] = v;
    __syncthreads();
    float wpre = 0.0f, total = 0.0f;
    #pragma unroll
    for (int w = 0; w < 8; w++) {
        float s = wsum[w];
        if (w < warp) wpre += s;
        total += s;
    }
    const float off = total - (wpre + v);

    float lmax = -INFINITY;
    #pragma unroll
    for (int j = 0; j < 8; j++) {
        float pos = fminf(g[j] + off, (float)(NPOS - 1));
        float pf = floorf(pos);
        int fi = (int)pf;
        int ci = (int)ceilf(pos);
        float w = pos - pf;
        x[j] += li[ci] * w + li[fi] * (1.0f - w);
        lmax = fmaxf(lmax, x[j]);
    }
    #pragma unroll
    for (int d = 16; d > 0; d >>= 1)
        lmax = fmaxf(lmax, __shfl_xor_sync(0xffffffffu, lmax, d));
    if (lane == 0) redm[warp] = lmax;
    __syncthreads();
    float mx = redm[0];
    #pragma unroll
    for (int w = 1; w < 8; w++) mx = fmaxf(mx, redm[w]);

    float lsum = 0.0f;
    #pragma unroll
    for (int j = 0; j < 8; j++) {
        x[j] = __expf(x[j] - mx);
        lsum += x[j];
    }
    #pragma unroll
    for (int d = 16; d > 0; d >>= 1)
        lsum += __shfl_xor_sync(0xffffffffu, lsum, d);
    if (lane == 0) reds[warp] = lsum;
    __syncthreads();
    float tsum = 0.0f;
    #pragma unroll
    for (int w = 0; w < 8; w++) tsum += reds[w];
    const float inv = 1.0f / tsum;

    bf16* sh = g_Sh + rbase + base;
    bf16* sl = g_Sl + rbase + base;
    #pragma unroll
    for (int jp = 0; jp < 4; jp++) {
        float a = x[2 * jp] * inv, b = x[2 * jp + 1] * inv;
        bf16 ha = __float2bfloat16_rn(a), hb = __float2bfloat16_rn(b);
        ((bf162*)sh)[jp] = bf162{ha, hb};
        ((bf162*)sl)[jp] = bf162{__float2bfloat16_rn(a - __bfloat162float(ha)),
                                 __float2bfloat16_rn(b - __bfloat162float(hb))};
    }
}

// -------- ctx = scores @ V (split-bf16, cp.async 3-stage) -------------------
// Block 128(q) x 64(n=head), BK=32, 8 warps (32x32). 2 CTAs/SM.
#define CXST  40
#define CXVST 72
#define CX_SH 0
#define CX_SL (128 * CXST)
#define CX_VH (256 * CXST)
#define CX_VL (256 * CXST + 32 * CXVST)
#define CX_STAGE (256 * CXST + 64 * CXVST)   // elems (29696 B)
#define CX_SMEM  (3 * CX_STAGE * 2)          // 89088 bytes

__global__ __launch_bounds__(256, 2) void ctx_kernel()
{
    extern __shared__ bf16 cxs[];
    const int tid = threadIdx.x, lane = tid & 31, warp = tid >> 5;
    const int wm = warp & 3, wn = warp >> 2;
    const int h = blockIdx.y;
    const int q0 = blockIdx.x * 128;
    const int ho = h * DH;
    const bf16* Sh = g_Sh + (size_t)h * SEQ * SEQ;
    const bf16* Sl = g_Sl + (size_t)h * SEQ * SEQ;

    const int sr = tid >> 1, sc = (tid & 1) * 16;
    const int vr = tid >> 3, vc = (tid & 7) * 8;

    #define CX_LOAD(kt, s)                                                        \
        { bf16* st = cxs + (s) * CX_STAGE;                                        \
          cp16(smem_u32(&st[CX_SH + sr * CXST + sc]),                             \
               &Sh[(size_t)(q0 + sr) * SEQ + (kt) + sc]);                         \
          cp16(smem_u32(&st[CX_SH + sr * CXST + sc + 8]),                         \
               &Sh[(size_t)(q0 + sr) * SEQ + (kt) + sc + 8]);                     \
          cp16(smem_u32(&st[CX_SL + sr * CXST + sc]),                             \
               &Sl[(size_t)(q0 + sr) * SEQ + (kt) + sc]);                         \
          cp16(smem_u32(&st[CX_SL + sr * CXST + sc + 8]),                         \
               &Sl[(size_t)(q0 + sr) * SEQ + (kt) + sc + 8]);                     \
          cp16(smem_u32(&st[CX_VH + vr * CXVST + vc]),                            \
               &g_Vh[(size_t)((kt) + vr) * ND + ho + vc]);                        \
          cp16(smem_u32(&st[CX_VL + vr * CXVST + vc]),                            \
               &g_Vl[(size_t)((kt) + vr) * ND + ho + vc]);                        \
          CP_COMMIT(); }

    float acc[2][4][4] = {};
    CX_LOAD(0, 0);
    CX_LOAD(32, 1);
    int s = 0;
    for (int kt = 0; kt < SEQ; kt += 32) {
        if (kt + 64 < SEQ) {
            int sn = s + 2; if (sn >= 3) sn -= 3;
            CX_LOAD(kt + 64, sn);
            CP_WAIT2();
        } else if (kt + 32 < SEQ) {
            CP_WAIT1();
        } else {
            CP_WAIT0();
        }
        __syncthreads();
        bf16* st = cxs + s * CX_STAGE;
        #pragma unroll
        for (int kk = 0; kk < 32; kk += 16) {
            uint32_t Ah[2][4], Al[2][4];
            int arow = wm * 32 + (lane & 7) + ((lane >> 3) & 1) * 8;
            int acol = kk + (lane >> 4) * 8;
            ldsm4(Ah[0], smem_u32(&st[CX_SH + arow * CXST + acol]));
            ldsm4(Ah[1], smem_u32(&st[CX_SH + (arow + 16) * CXST + acol]));
            ldsm4(Al[0], smem_u32(&st[CX_SL + arow * CXST + acol]));
            ldsm4(Al[1], smem_u32(&st[CX_SL + (arow + 16) * CXST + acol]));
            #pragma unroll
            for (int nt2 = 0; nt2 < 2; nt2++) {
                uint32_t Bh[4], Bl[4];
                int vrow = kk + ((lane >> 3) & 1) * 8 + (lane & 7);
                int vcol = wn * 32 + nt2 * 16 + (lane >> 4) * 8;
                ldsm4t(Bh, smem_u32(&st[CX_VH + vrow * CXVST + vcol]));
                ldsm4t(Bl, smem_u32(&st[CX_VL + vrow * CXVST + vcol]));
                #pragma unroll
                for (int mt = 0; mt < 2; mt++)
                    #pragma unroll
                    for (int p = 0; p < 2; p++) {
                        mma16816(acc[mt][nt2 * 2 + p], Ah[mt], &Bh[p * 2]);
                        mma16816(acc[mt][nt2 * 2 + p], Ah[mt], &Bl[p * 2]);
                        mma16816(acc[mt][nt2 * 2 + p], Al[mt], &Bh[p * 2]);
                    }
            }
        }
        __syncthreads();
        s = (s + 1 >= 3) ? 0 : s + 1;
    }

    const int r0 = lane >> 2, cc = (lane & 3) * 2;
    #pragma unroll
    for (int mt = 0; mt < 2; mt++)
        #pragma unroll
        for (int nt = 0; nt < 4; nt++) {
            int m = q0 + wm * 32 + mt * 16 + r0;
            int n = ho + wn * 32 + nt * 8 + cc;
            float v0 = acc[mt][nt][0], v1 = acc[mt][nt][1];
            float v2 = acc[mt][nt][2], v3 = acc[mt][nt][3];
            bf16 h0 = __float2bfloat16_rn(v0), h1 = __float2bfloat16_rn(v1);
            bf16 h2 = __float2bfloat16_rn(v2), h3 = __float2bfloat16_rn(v3);
            *(bf162*)&g_ctxh[(size_t)m * ND + n]       = bf162{h0, h1};
            *(bf162*)&g_ctxh[(size_t)(m + 8) * ND + n] = bf162{h2, h3};
            *(bf162*)&g_ctxl[(size_t)m * ND + n] =
                bf162{__float2bfloat16_rn(v0 - __bfloat162float(h0)),
                      __float2bfloat16_rn(v1 - __bfloat162float(h1))};
            *(bf162*)&g_ctxl[(size_t)(m + 8) * ND + n] =
                bf162{__float2bfloat16_rn(v2 - __bfloat162float(h2)),
                      __float2bfloat16_rn(v3 - __bfloat162float(h3))};
        }
}

// ---------------------------------------------------------------------------
extern "C" void kernel_launch(void* const* d_in, const int* in_sizes, int n_in,
                              void* d_out, int out_size)
{
    const float* q      = (const float*)d_in[0];
    const float* k      = (const float*)d_in[1];
    const float* v      = (const float*)d_in[2];
    const float* Wq_w   = (const float*)d_in[3];
    const float* Wq_b   = (const float*)d_in[4];
    const float* Wk_w   = (const float*)d_in[5];
    const float* Wk_b   = (const float*)d_in[6];
    const float* Wv_w   = (const float*)d_in[7];
    const float* Wv_b   = (const float*)d_in[8];
    const float* Wo_w   = (const float*)d_in[9];
    const float* Wo_b   = (const float*)d_in[10];
    const float* pos_emb= (const float*)d_in[11];
    float* out = (float*)d_out;

    static bool attr_set = false;
    if (!attr_set) {
        cudaFuncSetAttribute(mm_bias_kernel,
                             cudaFuncAttributeMaxDynamicSharedMemorySize, MM_SMEM);
        cudaFuncSetAttribute(qk_kernel,
                             cudaFuncAttributeMaxDynamicSharedMemorySize, QK_SMEM);
        cudaFuncSetAttribute(ctx_kernel,
                             cudaFuncAttributeMaxDynamicSharedMemorySize, CX_SMEM);
        attr_set = true;
    }

    bf16 *inqh, *inql, *inkh, *inkl, *invh, *invl;
    bf16 *wqh, *wql, *wkh, *wkl, *wvh, *wvl, *woh, *wol;
    bf16 *Qh, *Ql, *Kh, *Kl, *Vh, *Vl, *ctxh, *ctxl;
    float* Qf;
    cudaGetSymbolAddress((void**)&inqh, g_inqh); cudaGetSymbolAddress((void**)&inql, g_inql);
    cudaGetSymbolAddress((void**)&inkh, g_inkh); cudaGetSymbolAddress((void**)&inkl, g_inkl);
    cudaGetSymbolAddress((void**)&invh, g_invh); cudaGetSymbolAddress((void**)&invl, g_invl);
    cudaGetSymbolAddress((void**)&wqh, g_wqh);   cudaGetSymbolAddress((void**)&wql, g_wql);
    cudaGetSymbolAddress((void**)&wkh, g_wkh);   cudaGetSymbolAddress((void**)&wkl, g_wkl);
    cudaGetSymbolAddress((void**)&wvh, g_wvh);   cudaGetSymbolAddress((void**)&wvl, g_wvl);
    cudaGetSymbolAddress((void**)&woh, g_woh);   cudaGetSymbolAddress((void**)&wol, g_wol);
    cudaGetSymbolAddress((void**)&Qh, g_Qh);     cudaGetSymbolAddress((void**)&Ql, g_Ql);
    cudaGetSymbolAddress((void**)&Kh, g_Kh);     cudaGetSymbolAddress((void**)&Kl, g_Kl);
    cudaGetSymbolAddress((void**)&Vh, g_Vh);     cudaGetSymbolAddress((void**)&Vl, g_Vl);
    cudaGetSymbolAddress((void**)&ctxh, g_ctxh); cudaGetSymbolAddress((void**)&ctxl, g_ctxl);
    cudaGetSymbolAddress((void**)&Qf, g_Q);

    const int nIn = SEQ * ND / 1024;
    const int nW  = ND * ND / 1024;

    split3_kernel<<<dim3(nIn, 3), 256>>>(q, k, v,
                                         inqh, inql, inkh, inkl, invh, invl);
    split4_kernel<<<dim3(nW, 4), 256>>>(Wq_w, Wk_w, Wv_w, Wo_w,
                                        wqh, wql, wkh, wkl, wvh, wvl, woh, wol);

    MMJob jq{inqh, inql, wqh, wql, Wq_b, Qf, Qh, Ql};
    MMJob jk{inkh, inkl, wkh, wkl, Wk_b, nullptr, Kh, Kl};
    MMJob jv{invh, invl, wvh, wvl, Wv_b, nullptr, Vh, Vl};
    MMJob jo{ctxh, ctxl, woh, wol, Wo_b, out, nullptr, nullptr};

    dim3 gProj3(ND / 64, SEQ / 128, 3);   // (16, 16, 3) = 768 CTAs
    mm_bias_kernel<<<gProj3, 256, MM_SMEM>>>(jq, jk, jv);

    qk_kernel<<<dim3(SEQ / 128, SEQ / 128, NH), 256, QK_SMEM>>>();
    li_kernel<<<dim3(SEQ / 64, NH), 256>>>(pos_emb);
    cope_softmax_kernel<<<dim3(SEQ, NH), 256>>>();
    ctx_kernel<<<dim3(SEQ / 128, NH), 256, CX_SMEM>>>();

    dim3 gProj1(ND / 64, SEQ / 128, 1);
    mm_bias_kernel<<<gProj1, 256, MM_SMEM>>>(jo, jo, jo);
}

// round 15
// speedup vs baseline: 1.4903x; 1.1888x over previous
#include <cuda_runtime.h>
#include <cuda_bf16.h>
#include <cuda_fp16.h>
#include <math.h>
#include <stdint.h>

#define SEQ   2048
#define ND    1024
#define NH    16
#define DH    64
#define NPOS  64

typedef __nv_bfloat16 bf16;
typedef __nv_bfloat162 bf162;

// ---------------- scratch (device globals: allocation-free) ----------------
__device__ float g_Q[SEQ * ND];
__device__ float g_logits[(size_t)NH * SEQ * SEQ];    // 256 MB fp32 logits
__device__ float g_li[NH * SEQ * NPOS];

__device__ bf16 g_inqh[SEQ * ND], g_inql[SEQ * ND];
__device__ bf16 g_inkh[SEQ * ND], g_inkl[SEQ * ND];
__device__ bf16 g_invh[SEQ * ND], g_invl[SEQ * ND];
__device__ bf16 g_wqh[ND * ND], g_wql[ND * ND];
__device__ bf16 g_wkh[ND * ND], g_wkl[ND * ND];
__device__ bf16 g_wvh[ND * ND], g_wvl[ND * ND];
__device__ bf16 g_woh[ND * ND], g_wol[ND * ND];
__device__ bf16 g_Qh[SEQ * ND], g_Ql[SEQ * ND];
__device__ bf16 g_Kh[SEQ * ND], g_Kl[SEQ * ND];
__device__ __half g_Vh[SEQ * ND], g_Vl[SEQ * ND];     // V split in fp16
__device__ bf16 g_ctxh[SEQ * ND], g_ctxl[SEQ * ND];
__device__ __half g_Sf[(size_t)NH * SEQ * SEQ];       // scores fp16 (134 MB)

// ---------------- PTX helpers ----------------------------------------------
__device__ __forceinline__ uint32_t smem_u32(const void* p) {
    return (uint32_t)__cvta_generic_to_shared(p);
}
__device__ __forceinline__ void ldsm4(uint32_t* r, uint32_t a) {
    asm volatile("ldmatrix.sync.aligned.m8n8.x4.shared.b16 {%0,%1,%2,%3}, [%4];"
                 : "=r"(r[0]), "=r"(r[1]), "=r"(r[2]), "=r"(r[3]) : "r"(a));
}
__device__ __forceinline__ void ldsm4t(uint32_t* r, uint32_t a) {
    asm volatile("ldmatrix.sync.aligned.m8n8.x4.trans.shared.b16 {%0,%1,%2,%3}, [%4];"
                 : "=r"(r[0]), "=r"(r[1]), "=r"(r[2]), "=r"(r[3]) : "r"(a));
}
__device__ __forceinline__ void mma16816(float* c, const uint32_t* a, const uint32_t* b) {
    asm volatile(
        "mma.sync.aligned.m16n8k16.row.col.f32.bf16.bf16.f32 "
        "{%0,%1,%2,%3}, {%4,%5,%6,%7}, {%8,%9}, {%0,%1,%2,%3};"
        : "+f"(c[0]), "+f"(c[1]), "+f"(c[2]), "+f"(c[3])
        : "r"(a[0]), "r"(a[1]), "r"(a[2]), "r"(a[3]), "r"(b[0]), "r"(b[1]));
}
__device__ __forceinline__ void mma16816h(float* c, const uint32_t* a, const uint32_t* b) {
    asm volatile(
        "mma.sync.aligned.m16n8k16.row.col.f32.f16.f16.f32 "
        "{%0,%1,%2,%3}, {%4,%5,%6,%7}, {%8,%9}, {%0,%1,%2,%3};"
        : "+f"(c[0]), "+f"(c[1]), "+f"(c[2]), "+f"(c[3])
        : "r"(a[0]), "r"(a[1]), "r"(a[2]), "r"(a[3]), "r"(b[0]), "r"(b[1]));
}
__device__ __forceinline__ void cp16(uint32_t sa, const void* g) {
    asm volatile("cp.async.cg.shared.global [%0], [%1], 16;" :: "r"(sa), "l"(g));
}
#define CP_COMMIT() asm volatile("cp.async.commit_group;" ::: "memory")
#define CP_WAIT2()  asm volatile("cp.async.wait_group 2;" ::: "memory")
#define CP_WAIT1()  asm volatile("cp.async.wait_group 1;" ::: "memory")
#define CP_WAIT0()  asm volatile("cp.async.wait_group 0;" ::: "memory")

// ---------------- split fp32 -> bf16 hi + bf16 lo (batched) -----------------
__device__ __forceinline__ void split_body(const float* __restrict__ s,
                                           bf16* __restrict__ hi, bf16* __restrict__ lo)
{
    int i = (blockIdx.x * 256 + threadIdx.x) * 4;
    float4 v = *(const float4*)&s[i];
    bf16 h0 = __float2bfloat16_rn(v.x), h1 = __float2bfloat16_rn(v.y);
    bf16 h2 = __float2bfloat16_rn(v.z), h3 = __float2bfloat16_rn(v.w);
    bf16 l0 = __float2bfloat16_rn(v.x - __bfloat162float(h0));
    bf16 l1 = __float2bfloat16_rn(v.y - __bfloat162float(h1));
    bf16 l2 = __float2bfloat16_rn(v.z - __bfloat162float(h2));
    bf16 l3 = __float2bfloat16_rn(v.w - __bfloat162float(h3));
    *(bf162*)&hi[i]     = bf162{h0, h1};
    *(bf162*)&hi[i + 2] = bf162{h2, h3};
    *(bf162*)&lo[i]     = bf162{l0, l1};
    *(bf162*)&lo[i + 2] = bf162{l2, l3};
}

__global__ __launch_bounds__(256) void split3_kernel(
    const float* s0, const float* s1, const float* s2,
    bf16* h0, bf16* l0, bf16* h1, bf16* l1, bf16* h2, bf16* l2)
{
    const float* s = (blockIdx.y == 0) ? s0 : (blockIdx.y == 1) ? s1 : s2;
    bf16* hp = (blockIdx.y == 0) ? h0 : (blockIdx.y == 1) ? h1 : h2;
    bf16* lp = (blockIdx.y == 0) ? l0 : (blockIdx.y == 1) ? l1 : l2;
    split_body(s, hp, lp);
}

__global__ __launch_bounds__(256) void split4_kernel(
    const float* s0, const float* s1, const float* s2, const float* s3,
    bf16* h0, bf16* l0, bf16* h1, bf16* l1,
    bf16* h2, bf16* l2, bf16* h3, bf16* l3)
{
    const float* s = (blockIdx.y == 0) ? s0 : (blockIdx.y == 1) ? s1 :
                     (blockIdx.y == 2) ? s2 : s3;
    bf16* hp = (blockIdx.y == 0) ? h0 : (blockIdx.y == 1) ? h1 :
               (blockIdx.y == 2) ? h2 : h3;
    bf16* lp = (blockIdx.y == 0) ? l0 : (blockIdx.y == 1) ? l1 :
               (blockIdx.y == 2) ? l2 : l3;
    split_body(s, hp, lp);
}

// ---------------- Y = X @ W^T + bias (split-bf16, cp.async 3-stage) ---------
// Block 128(m) x 64(n), BK=32, 8 warps (warp tile 32x32). 2 CTAs/SM.
struct MMJob {
    const bf16 *Xh, *Xl, *Wh, *Wl;
    const float* bias;
    float* Yf;
    void *Yh, *Yl;      // bf16* or __half* depending on f16 flag
    int f16;
};

#define MMST 40
#define MM_XH 0
#define MM_XL (128 * MMST)
#define MM_WH (256 * MMST)
#define MM_WL (320 * MMST)
#define MM_STAGE (384 * MMST)
#define MM_SMEM  (3 * MM_STAGE * 2)      // 92160 bytes

__global__ __launch_bounds__(256, 2) void mm_bias_kernel(MMJob j0, MMJob j1, MMJob j2)
{
    extern __shared__ bf16 mms[];
    const MMJob j = (blockIdx.z == 0) ? j0 : (blockIdx.z == 1) ? j1 : j2;
    const bf16* __restrict__ Xh = j.Xh;
    const bf16* __restrict__ Xl = j.Xl;
    const bf16* __restrict__ Wh = j.Wh;
    const bf16* __restrict__ Wl = j.Wl;

    const int tid = threadIdx.x, lane = tid & 31, warp = tid >> 5;
    const int wm = warp & 3, wn = warp >> 2;
    const int m0 = blockIdx.y * 128, n0 = blockIdx.x * 64;
    const int xr = tid >> 2, xc = (tid & 3) * 8;

    #define MM_LOAD(kt, s)                                                        \
        { bf16* st = mms + (s) * MM_STAGE;                                        \
          cp16(smem_u32(&st[MM_XH + xr * MMST + xc]),                             \
               &Xh[(size_t)(m0 + xr) * ND + (kt) + xc]);                          \
          cp16(smem_u32(&st[MM_XH + (xr + 64) * MMST + xc]),                      \
               &Xh[(size_t)(m0 + xr + 64) * ND + (kt) + xc]);                     \
          cp16(smem_u32(&st[MM_XL + xr * MMST + xc]),                             \
               &Xl[(size_t)(m0 + xr) * ND + (kt) + xc]);                          \
          cp16(smem_u32(&st[MM_XL + (xr + 64) * MMST + xc]),                      \
               &Xl[(size_t)(m0 + xr + 64) * ND + (kt) + xc]);                     \
          cp16(smem_u32(&st[MM_WH + xr * MMST + xc]),                             \
               &Wh[(size_t)(n0 + xr) * ND + (kt) + xc]);                          \
          cp16(smem_u32(&st[MM_WL + xr * MMST + xc]),                             \
               &Wl[(size_t)(n0 + xr) * ND + (kt) + xc]);                          \
          CP_COMMIT(); }

    float acc[2][4][4] = {};
    MM_LOAD(0, 0);
    MM_LOAD(32, 1);
    int s = 0;
    for (int kt = 0; kt < ND; kt += 32) {
        if (kt + 64 < ND) {
            int sn = s + 2; if (sn >= 3) sn -= 3;
            MM_LOAD(kt + 64, sn);
            CP_WAIT2();
        } else if (kt + 32 < ND) {
            CP_WAIT1();
        } else {
            CP_WAIT0();
        }
        __syncthreads();
        bf16* st = mms + s * MM_STAGE;
        #pragma unroll
        for (int kk = 0; kk < 32; kk += 16) {
            uint32_t Ah[2][4], Al[2][4];
            int arow = wm * 32 + (lane & 7) + ((lane >> 3) & 1) * 8;
            int acol = kk + (lane >> 4) * 8;
            ldsm4(Ah[0], smem_u32(&st[MM_XH + arow * MMST + acol]));
            ldsm4(Ah[1], smem_u32(&st[MM_XH + (arow + 16) * MMST + acol]));
            ldsm4(Al[0], smem_u32(&st[MM_XL + arow * MMST + acol]));
            ldsm4(Al[1], smem_u32(&st[MM_XL + (arow + 16) * MMST + acol]));
            #pragma unroll
            for (int nt2 = 0; nt2 < 2; nt2++) {
                uint32_t Bh[4], Bl[4];
                int brow = wn * 32 + nt2 * 16 + (lane >> 4) * 8 + (lane & 7);
                int bcol = kk + ((lane >> 3) & 1) * 8;
                ldsm4(Bh, smem_u32(&st[MM_WH + brow * MMST + bcol]));
                ldsm4(Bl, smem_u32(&st[MM_WL + brow * MMST + bcol]));
                #pragma unroll
                for (int mt = 0; mt < 2; mt++)
                    #pragma unroll
                    for (int p = 0; p < 2; p++) {
                        mma16816(acc[mt][nt2 * 2 + p], Ah[mt], &Bh[p * 2]);
                        mma16816(acc[mt][nt2 * 2 + p], Ah[mt], &Bl[p * 2]);
                        mma16816(acc[mt][nt2 * 2 + p], Al[mt], &Bh[p * 2]);
                    }
            }
        }
        __syncthreads();
        s = (s + 1 >= 3) ? 0 : s + 1;
    }

    const int r0 = lane >> 2, cc = (lane & 3) * 2;
    #pragma unroll
    for (int mt = 0; mt < 2; mt++)
        #pragma unroll
        for (int nt = 0; nt < 4; nt++) {
            int m = m0 + wm * 32 + mt * 16 + r0;
            int n = n0 + wn * 32 + nt * 8 + cc;
            float b0 = j.bias[n], b1 = j.bias[n + 1];
            float v0 = acc[mt][nt][0] + b0, v1 = acc[mt][nt][1] + b1;
            float v2 = acc[mt][nt][2] + b0, v3 = acc[mt][nt][3] + b1;
            if (j.Yf) {
                *(float2*)&j.Yf[(size_t)m * ND + n]       = float2{v0, v1};
                *(float2*)&j.Yf[(size_t)(m + 8) * ND + n] = float2{v2, v3};
            }
            if (j.Yh) {
                if (j.f16) {
                    __half* Yh = (__half*)j.Yh;
                    __half* Yl = (__half*)j.Yl;
                    __half h0 = __float2half_rn(v0), h1 = __float2half_rn(v1);
                    __half h2 = __float2half_rn(v2), h3 = __float2half_rn(v3);
                    *(__half2*)&Yh[(size_t)m * ND + n]       = __halves2half2(h0, h1);
                    *(__half2*)&Yh[(size_t)(m + 8) * ND + n] = __halves2half2(h2, h3);
                    *(__half2*)&Yl[(size_t)m * ND + n] =
                        __halves2half2(__float2half_rn(v0 - __half2float(h0)),
                                       __float2half_rn(v1 - __half2float(h1)));
                    *(__half2*)&Yl[(size_t)(m + 8) * ND + n] =
                        __halves2half2(__float2half_rn(v2 - __half2float(h2)),
                                       __float2half_rn(v3 - __half2float(h3)));
                } else {
                    bf16* Yh = (bf16*)j.Yh;
                    bf16* Yl = (bf16*)j.Yl;
                    bf16 h0 = __float2bfloat16_rn(v0), h1 = __float2bfloat16_rn(v1);
                    bf16 h2 = __float2bfloat16_rn(v2), h3 = __float2bfloat16_rn(v3);
                    *(bf162*)&Yh[(size_t)m * ND + n]       = bf162{h0, h1};
                    *(bf162*)&Yh[(size_t)(m + 8) * ND + n] = bf162{h2, h3};
                    *(bf162*)&Yl[(size_t)m * ND + n] =
                        bf162{__float2bfloat16_rn(v0 - __bfloat162float(h0)),
                              __float2bfloat16_rn(v1 - __bfloat162float(h1))};
                    *(bf162*)&Yl[(size_t)(m + 8) * ND + n] =
                        bf162{__float2bfloat16_rn(v2 - __bfloat162float(h2)),
                              __float2bfloat16_rn(v3 - __bfloat162float(h3))};
                }
            }
        }
}

// ---------------- logits = 0.125 * Q K^T (per head) -------------------------
#define QKS 72
#define QK_QH 0
#define QK_QL (QK_QH + 128 * QKS * 2)
#define QK_KH (QK_QL + 128 * QKS * 2)
#define QK_KL (QK_KH + 128 * QKS * 2)
#define QK_SMEM (QK_KL + 128 * QKS * 2)

__global__ __launch_bounds__(256) void qk_kernel()
{
    extern __shared__ char sm[];
    bf16* Qsh = (bf16*)(sm + QK_QH);
    bf16* Qsl = (bf16*)(sm + QK_QL);
    bf16* Ksh = (bf16*)(sm + QK_KH);
    bf16* Ksl = (bf16*)(sm + QK_KL);

    const int tid = threadIdx.x, lane = tid & 31, warp = tid >> 5;
    const int wm = warp & 3, wn = warp >> 2;
    const int h = blockIdx.z;
    const int q0 = blockIdx.y * 128, k0 = blockIdx.x * 128;
    const int ho = h * DH;

    const int lr = tid >> 2, lc = (tid & 3) * 16;
    #pragma unroll
    for (int it = 0; it < 2; it++) {
        int r = lr + it * 64;
        *(uint4*)&Qsh[r * QKS + lc]     = *(const uint4*)&g_Qh[(size_t)(q0 + r) * ND + ho + lc];
        *(uint4*)&Qsh[r * QKS + lc + 8] = *(const uint4*)&g_Qh[(size_t)(q0 + r) * ND + ho + lc + 8];
        *(uint4*)&Qsl[r * QKS + lc]     = *(const uint4*)&g_Ql[(size_t)(q0 + r) * ND + ho + lc];
        *(uint4*)&Qsl[r * QKS + lc + 8] = *(const uint4*)&g_Ql[(size_t)(q0 + r) * ND + ho + lc + 8];
        *(uint4*)&Ksh[r * QKS + lc]     = *(const uint4*)&g_Kh[(size_t)(k0 + r) * ND + ho + lc];
        *(uint4*)&Ksh[r * QKS + lc + 8] = *(const uint4*)&g_Kh[(size_t)(k0 + r) * ND + ho + lc + 8];
        *(uint4*)&Ksl[r * QKS + lc]     = *(const uint4*)&g_Kl[(size_t)(k0 + r) * ND + ho + lc];
        *(uint4*)&Ksl[r * QKS + lc + 8] = *(const uint4*)&g_Kl[(size_t)(k0 + r) * ND + ho + lc + 8];
    }
    __syncthreads();

    float acc[2][8][4] = {};
    #pragma unroll
    for (int kk = 0; kk < 64; kk += 16) {
        uint32_t Ah[2][4], Al[2][4];
        int arow = wm * 32 + (lane & 7) + ((lane >> 3) & 1) * 8;
        int acol = kk + (lane >> 4) * 8;
        ldsm4(Ah[0], smem_u32(&Qsh[arow * QKS + acol]));
        ldsm4(Ah[1], smem_u32(&Qsh[(arow + 16) * QKS + acol]));
        ldsm4(Al[0], smem_u32(&Qsl[arow * QKS + acol]));
        ldsm4(Al[1], smem_u32(&Qsl[(arow + 16) * QKS + acol]));
        #pragma unroll
        for (int nt2 = 0; nt2 < 4; nt2++) {
            uint32_t Bh[4], Bl[4];
            int brow = wn * 64 + nt2 * 16 + (lane >> 4) * 8 + (lane & 7);
            int bcol = kk + ((lane >> 3) & 1) * 8;
            ldsm4(Bh, smem_u32(&Ksh[brow * QKS + bcol]));
            ldsm4(Bl, smem_u32(&Ksl[brow * QKS + bcol]));
            #pragma unroll
            for (int mt = 0; mt < 2; mt++)
                #pragma unroll
                for (int p = 0; p < 2; p++) {
                    mma16816(acc[mt][nt2 * 2 + p], Ah[mt], &Bh[p * 2]);
                    mma16816(acc[mt][nt2 * 2 + p], Ah[mt], &Bl[p * 2]);
                    mma16816(acc[mt][nt2 * 2 + p], Al[mt], &Bh[p * 2]);
                }
        }
    }

    float* out = g_logits + (size_t)h * SEQ * SEQ;
    const int r0 = lane >> 2, cc = (lane & 3) * 2;
    #pragma unroll
    for (int mt = 0; mt < 2; mt++)
        #pragma unroll
        for (int nt = 0; nt < 8; nt++) {
            int m = q0 + wm * 32 + mt * 16 + r0;
            int n = k0 + wn * 64 + nt * 8 + cc;
            *(float2*)&out[(size_t)m * SEQ + n] =
                float2{acc[mt][nt][0] * 0.125f, acc[mt][nt][1] * 0.125f};
            *(float2*)&out[(size_t)(m + 8) * SEQ + n] =
                float2{acc[mt][nt][2] * 0.125f, acc[mt][nt][3] * 0.125f};
        }
}

// -------- li[h,q,n] = sum_d Q[q, h*64+d] * pos_emb[d, n] --------------------
__global__ __launch_bounds__(256) void li_kernel(const float* __restrict__ pos_emb)
{
    __shared__ float Qs[64][65];
    __shared__ float Ps[64][65];
    const int tid = threadIdx.x;
    const int tx = tid & 15, ty = tid >> 4;
    const int h = blockIdx.y;
    const int q0 = blockIdx.x * 64;

    for (int i = tid; i < 64 * 64; i += 256) {
        int r = i >> 6, c = i & 63;
        Qs[r][c] = g_Q[(q0 + r) * ND + h * DH + c];
        Ps[r][c] = pos_emb[r * NPOS + c];
    }
    __syncthreads();

    float acc[4][4] = {};
    #pragma unroll 8
    for (int d = 0; d < 64; d++) {
        float a[4], b[4];
        #pragma unroll
        for (int i = 0; i < 4; i++) a[i] = Qs[ty * 4 + i][d];
        #pragma unroll
        for (int j = 0; j < 4; j++) b[j] = Ps[d][tx * 4 + j];
        #pragma unroll
        for (int i = 0; i < 4; i++)
            #pragma unroll
            for (int j = 0; j < 4; j++) acc[i][j] += a[i] * b[j];
    }
    #pragma unroll
    for (int i = 0; i < 4; i++)
        #pragma unroll
        for (int j = 0; j < 4; j++)
            g_li[(h * SEQ + q0 + ty * 4 + i) * NPOS + tx * 4 + j] = acc[i][j];
}

// -------- per (h,q) row: gates -> suffix-cumsum -> CoPE -> softmax ----------
// Writes scores as ONE fp16 array.
__global__ __launch_bounds__(256) void cope_softmax_kernel()
{
    __shared__ float li[NPOS];
    __shared__ float wsum[8];
    __shared__ float redm[8];
    __shared__ float reds[8];

    const int tid = threadIdx.x;
    const int lane = tid & 31, warp = tid >> 5;
    const int q = blockIdx.x, h = blockIdx.y;
    const size_t rbase = ((size_t)h * SEQ + q) * SEQ;
    const float* lrow = g_logits + rbase;

    if (tid < NPOS) li[tid] = g_li[(h * SEQ + q) * NPOS + tid];

    const int base = tid * 8;
    float x[8];
    *(float4*)&x[0] = *(const float4*)&lrow[base];
    *(float4*)&x[4] = *(const float4*)&lrow[base + 4];

    float g[8];
    float csum = 0.0f;
    #pragma unroll
    for (int j = 7; j >= 0; --j) {
        float t;
        asm("tanh.approx.f32 %0, %1;" : "=f"(t) : "f"(x[j] * 0.5f));
        csum += fmaf(t, 0.5f, 0.5f);
        g[j] = csum;
    }
    float v = csum;
    #pragma unroll
    for (int d = 1; d < 32; d <<= 1) {
        float n = __shfl_up_sync(0xffffffffu, v, d);
        if (lane >= d) v += n;
    }
    if (lane == 31) wsum[warp] = v;
    __syncthreads();
    float wpre = 0.0f, total = 0.0f;
    #pragma unroll
    for (int w = 0; w < 8; w++) {
        float s = wsum[w];
        if (w < warp) wpre += s;
        total += s;
    }
    const float off = total - (wpre + v);

    float lmax = -INFINITY;
    #pragma unroll
    for (int j = 0; j < 8; j++) {
        float pos = fminf(g[j] + off, (float)(NPOS - 1));
        float pf = floorf(pos);
        int fi = (int)pf;
        int ci = (int)ceilf(pos);
        float w = pos - pf;
        x[j] += li[ci] * w + li[fi] * (1.0f - w);
        lmax = fmaxf(lmax, x[j]);
    }
    #pragma unroll
    for (int d = 16; d > 0; d >>= 1)
        lmax = fmaxf(lmax, __shfl_xor_sync(0xffffffffu, lmax, d));
    if (lane == 0) redm[warp] = lmax;
    __syncthreads();
    float mx = redm[0];
    #pragma unroll
    for (int w = 1; w < 8; w++) mx = fmaxf(mx, redm[w]);

    float lsum = 0.0f;
    #pragma unroll
    for (int j = 0; j < 8; j++) {
        x[j] = __expf(x[j] - mx);
        lsum += x[j];
    }
    #pragma unroll
    for (int d = 16; d > 0; d >>= 1)
        lsum += __shfl_xor_sync(0xffffffffu, lsum, d);
    if (lane == 0) reds[warp] = lsum;
    __syncthreads();
    float tsum = 0.0f;
    #pragma unroll
    for (int w = 0; w < 8; w++) tsum += reds[w];
    const float inv = 1.0f / tsum;

    __half hs[8];
    #pragma unroll
    for (int j = 0; j < 8; j++) hs[j] = __float2half_rn(x[j] * inv);
    *(uint4*)&g_Sf[rbase + base] = *(uint4*)hs;
}

// -------- ctx = S(fp16) @ V(fp16 hi/lo), cp.async 3-stage -------------------
// Block 128(q) x 64(n=head), BK=32, 8 warps (32x32). 2 CTAs/SM. 2 MMA terms.
#define CXST  40
#define CXVST 72
#define CX_S  0
#define CX_VH (128 * CXST)
#define CX_VL (128 * CXST + 32 * CXVST)
#define CX_STAGE (128 * CXST + 64 * CXVST)   // 9728 halves (19456 B)
#define CX_SMEM  (3 * CX_STAGE * 2)          // 58368 bytes

__global__ __launch_bounds__(256, 2) void ctx_kernel()
{
    extern __shared__ __half cxs[];
    const int tid = threadIdx.x, lane = tid & 31, warp = tid >> 5;
    const int wm = warp & 3, wn = warp >> 2;
    const int h = blockIdx.y;
    const int q0 = blockIdx.x * 128;
    const int ho = h * DH;
    const __half* Sf = g_Sf + (size_t)h * SEQ * SEQ;

    const int sr = tid >> 1, sc = (tid & 1) * 16;   // S: 2 thr/row, 16 halves each
    const int vr = tid >> 3, vc = (tid & 7) * 8;    // V: 32 rows x 8-half chunks

    #define CX_LOAD(kt, s)                                                        \
        { __half* st = cxs + (s) * CX_STAGE;                                      \
          cp16(smem_u32(&st[CX_S + sr * CXST + sc]),                              \
               &Sf[(size_t)(q0 + sr) * SEQ + (kt) + sc]);                         \
          cp16(smem_u32(&st[CX_S + sr * CXST + sc + 8]),                          \
               &Sf[(size_t)(q0 + sr) * SEQ + (kt) + sc + 8]);                     \
          cp16(smem_u32(&st[CX_VH + vr * CXVST + vc]),                            \
               &g_Vh[(size_t)((kt) + vr) * ND + ho + vc]);                        \
          cp16(smem_u32(&st[CX_VL + vr * CXVST + vc]),                            \
               &g_Vl[(size_t)((kt) + vr) * ND + ho + vc]);                        \
          CP_COMMIT(); }

    float acc[2][4][4] = {};
    CX_LOAD(0, 0);
    CX_LOAD(32, 1);
    int s = 0;
    for (int kt = 0; kt < SEQ; kt += 32) {
        if (kt + 64 < SEQ) {
            int sn = s + 2; if (sn >= 3) sn -= 3;
            CX_LOAD(kt + 64, sn);
            CP_WAIT2();
        } else if (kt + 32 < SEQ) {
            CP_WAIT1();
        } else {
            CP_WAIT0();
        }
        __syncthreads();
        __half* st = cxs + s * CX_STAGE;
        #pragma unroll
        for (int kk = 0; kk < 32; kk += 16) {
            uint32_t A[2][4];
            int arow = wm * 32 + (lane & 7) + ((lane >> 3) & 1) * 8;
            int acol = kk + (lane >> 4) * 8;
            ldsm4(A[0], smem_u32(&st[CX_S + arow * CXST + acol]));
            ldsm4(A[1], smem_u32(&st[CX_S + (arow + 16) * CXST + acol]));
            #pragma unroll
            for (int nt2 = 0; nt2 < 2; nt2++) {
                uint32_t Bh[4], Bl[4];
                int vrow = kk + ((lane >> 3) & 1) * 8 + (lane & 7);
                int vcol = wn * 32 + nt2 * 16 + (lane >> 4) * 8;
                ldsm4t(Bh, smem_u32(&st[CX_VH + vrow * CXVST + vcol]));
                ldsm4t(Bl, smem_u32(&st[CX_VL + vrow * CXVST + vcol]));
                #pragma unroll
                for (int mt = 0; mt < 2; mt++)
                    #pragma unroll
                    for (int p = 0; p < 2; p++) {
                        mma16816h(acc[mt][nt2 * 2 + p], A[mt], &Bh[p * 2]);
                        mma16816h(acc[mt][nt2 * 2 + p], A[mt], &Bl[p * 2]);
                    }
            }
        }
        __syncthreads();
        s = (s + 1 >= 3) ? 0 : s + 1;
    }

    const int r0 = lane >> 2, cc = (lane & 3) * 2;
    #pragma unroll
    for (int mt = 0; mt < 2; mt++)
        #pragma unroll
        for (int nt = 0; nt < 4; nt++) {
            int m = q0 + wm * 32 + mt * 16 + r0;
            int n = ho + wn * 32 + nt * 8 + cc;
            float v0 = acc[mt][nt][0], v1 = acc[mt][nt][1];
            float v2 = acc[mt][nt][2], v3 = acc[mt][nt][3];
            bf16 h0 = __float2bfloat16_rn(v0), h1 = __float2bfloat16_rn(v1);
            bf16 h2 = __float2bfloat16_rn(v2), h3 = __float2bfloat16_rn(v3);
            *(bf162*)&g_ctxh[(size_t)m * ND + n]       = bf162{h0, h1};
            *(bf162*)&g_ctxh[(size_t)(m + 8) * ND + n] = bf162{h2, h3};
            *(bf162*)&g_ctxl[(size_t)m * ND + n] =
                bf162{__float2bfloat16_rn(v0 - __bfloat162float(h0)),
                      __float2bfloat16_rn(v1 - __bfloat162float(h1))};
            *(bf162*)&g_ctxl[(size_t)(m + 8) * ND + n] =
                bf162{__float2bfloat16_rn(v2 - __bfloat162float(h2)),
                      __float2bfloat16_rn(v3 - __bfloat162float(h3))};
        }
}

// ---------------------------------------------------------------------------
extern "C" void kernel_launch(void* const* d_in, const int* in_sizes, int n_in,
                              void* d_out, int out_size)
{
    const float* q      = (const float*)d_in[0];
    const float* k      = (const float*)d_in[1];
    const float* v      = (const float*)d_in[2];
    const float* Wq_w   = (const float*)d_in[3];
    const float* Wq_b   = (const float*)d_in[4];
    const float* Wk_w   = (const float*)d_in[5];
    const float* Wk_b   = (const float*)d_in[6];
    const float* Wv_w   = (const float*)d_in[7];
    const float* Wv_b   = (const float*)d_in[8];
    const float* Wo_w   = (const float*)d_in[9];
    const float* Wo_b   = (const float*)d_in[10];
    const float* pos_emb= (const float*)d_in[11];
    float* out = (float*)d_out;

    static bool attr_set = false;
    if (!attr_set) {
        cudaFuncSetAttribute(mm_bias_kernel,
                             cudaFuncAttributeMaxDynamicSharedMemorySize, MM_SMEM);
        cudaFuncSetAttribute(qk_kernel,
                             cudaFuncAttributeMaxDynamicSharedMemorySize, QK_SMEM);
        cudaFuncSetAttribute(ctx_kernel,
                             cudaFuncAttributeMaxDynamicSharedMemorySize, CX_SMEM);
        attr_set = true;
    }

    bf16 *inqh, *inql, *inkh, *inkl, *invh, *invl;
    bf16 *wqh, *wql, *wkh, *wkl, *wvh, *wvl, *woh, *wol;
    bf16 *Qh, *Ql, *Kh, *Kl, *ctxh, *ctxl;
    __half *Vh, *Vl;
    float* Qf;
    cudaGetSymbolAddress((void**)&inqh, g_inqh); cudaGetSymbolAddress((void**)&inql, g_inql);
    cudaGetSymbolAddress((void**)&inkh, g_inkh); cudaGetSymbolAddress((void**)&inkl, g_inkl);
    cudaGetSymbolAddress((void**)&invh, g_invh); cudaGetSymbolAddress((void**)&invl, g_invl);
    cudaGetSymbolAddress((void**)&wqh, g_wqh);   cudaGetSymbolAddress((void**)&wql, g_wql);
    cudaGetSymbolAddress((void**)&wkh, g_wkh);   cudaGetSymbolAddress((void**)&wkl, g_wkl);
    cudaGetSymbolAddress((void**)&wvh, g_wvh);   cudaGetSymbolAddress((void**)&wvl, g_wvl);
    cudaGetSymbolAddress((void**)&woh, g_woh);   cudaGetSymbolAddress((void**)&wol, g_wol);
    cudaGetSymbolAddress((void**)&Qh, g_Qh);     cudaGetSymbolAddress((void**)&Ql, g_Ql);
    cudaGetSymbolAddress((void**)&Kh, g_Kh);     cudaGetSymbolAddress((void**)&Kl, g_Kl);
    cudaGetSymbolAddress((void**)&Vh, g_Vh);     cudaGetSymbolAddress((void**)&Vl, g_Vl);
    cudaGetSymbolAddress((void**)&ctxh, g_ctxh); cudaGetSymbolAddress((void**)&ctxl, g_ctxl);
    cudaGetSymbolAddress((void**)&Qf, g_Q);

    const int nIn = SEQ * ND / 1024;
    const int nW  = ND * ND / 1024;

    split3_kernel<<<dim3(nIn, 3), 256>>>(q, k, v,
                                         inqh, inql, inkh, inkl, invh, invl);
    split4_kernel<<<dim3(nW, 4), 256>>>(Wq_w, Wk_w, Wv_w, Wo_w,
                                        wqh, wql, wkh, wkl, wvh, wvl, woh, wol);

    MMJob jq{inqh, inql, wqh, wql, Wq_b, Qf, Qh, Ql, 0};
    MMJob jk{inkh, inkl, wkh, wkl, Wk_b, nullptr, Kh, Kl, 0};
    MMJob jv{invh, invl, wvh, wvl, Wv_b, nullptr, Vh, Vl, 1};
    MMJob jo{ctxh, ctxl, woh, wol, Wo_b, out, nullptr, nullptr, 0};

    dim3 gProj3(ND / 64, SEQ / 128, 3);   // 768 CTAs
    mm_bias_kernel<<<gProj3, 256, MM_SMEM>>>(jq, jk, jv);

    qk_kernel<<<dim3(SEQ / 128, SEQ / 128, NH), 256, QK_SMEM>>>();
    li_kernel<<<dim3(SEQ / 64, NH), 256>>>(pos_emb);
    cope_softmax_kernel<<<dim3(SEQ, NH), 256>>>();
    ctx_kernel<<<dim3(SEQ / 128, NH), 256, CX_SMEM>>>();

    dim3 gProj1(ND / 64, SEQ / 128, 1);
    mm_bias_kernel<<<gProj1, 256, MM_SMEM>>>(jo, jo, jo);
}

// round 16
// speedup vs baseline: 1.5265x; 1.0243x over previous
#include <cuda_runtime.h>
#include <cuda_bf16.h>
#include <cuda_fp16.h>
#include <math.h>
#include <stdint.h>

#define SEQ   2048
#define ND    1024
#define NH    16
#define DH    64
#define NPOS  64

typedef __nv_bfloat16 bf16;
typedef __nv_bfloat162 bf162;

// ---------------- scratch (device globals: allocation-free) ----------------
__device__ float g_Q[SEQ * ND];
__device__ __half g_logith[(size_t)NH * SEQ * SEQ];   // 128 MB fp16 logits
__device__ float g_li[NH * SEQ * NPOS];

__device__ bf16 g_inqh[SEQ * ND], g_inql[SEQ * ND];
__device__ bf16 g_inkh[SEQ * ND], g_inkl[SEQ * ND];
__device__ bf16 g_invh[SEQ * ND], g_invl[SEQ * ND];
__device__ bf16 g_wqh[ND * ND], g_wql[ND * ND];
__device__ bf16 g_wkh[ND * ND], g_wkl[ND * ND];
__device__ bf16 g_wvh[ND * ND], g_wvl[ND * ND];
__device__ bf16 g_woh[ND * ND], g_wol[ND * ND];
__device__ bf16 g_Qh[SEQ * ND], g_Ql[SEQ * ND];
__device__ bf16 g_Kh[SEQ * ND], g_Kl[SEQ * ND];
__device__ __half g_Vh[SEQ * ND], g_Vl[SEQ * ND];     // V split in fp16
__device__ bf16 g_ctxh[SEQ * ND], g_ctxl[SEQ * ND];
__device__ __half g_Sf[(size_t)NH * SEQ * SEQ];       // scores fp16 (134 MB)

// ---------------- PTX helpers ----------------------------------------------
__device__ __forceinline__ uint32_t smem_u32(const void* p) {
    return (uint32_t)__cvta_generic_to_shared(p);
}
__device__ __forceinline__ void ldsm4(uint32_t* r, uint32_t a) {
    asm volatile("ldmatrix.sync.aligned.m8n8.x4.shared.b16 {%0,%1,%2,%3}, [%4];"
                 : "=r"(r[0]), "=r"(r[1]), "=r"(r[2]), "=r"(r[3]) : "r"(a));
}
__device__ __forceinline__ void ldsm4t(uint32_t* r, uint32_t a) {
    asm volatile("ldmatrix.sync.aligned.m8n8.x4.trans.shared.b16 {%0,%1,%2,%3}, [%4];"
                 : "=r"(r[0]), "=r"(r[1]), "=r"(r[2]), "=r"(r[3]) : "r"(a));
}
__device__ __forceinline__ void mma16816(float* c, const uint32_t* a, const uint32_t* b) {
    asm volatile(
        "mma.sync.aligned.m16n8k16.row.col.f32.bf16.bf16.f32 "
        "{%0,%1,%2,%3}, {%4,%5,%6,%7}, {%8,%9}, {%0,%1,%2,%3};"
        : "+f"(c[0]), "+f"(c[1]), "+f"(c[2]), "+f"(c[3])
        : "r"(a[0]), "r"(a[1]), "r"(a[2]), "r"(a[3]), "r"(b[0]), "r"(b[1]));
}
__device__ __forceinline__ void mma16816h(float* c, const uint32_t* a, const uint32_t* b) {
    asm volatile(
        "mma.sync.aligned.m16n8k16.row.col.f32.f16.f16.f32 "
        "{%0,%1,%2,%3}, {%4,%5,%6,%7}, {%8,%9}, {%0,%1,%2,%3};"
        : "+f"(c[0]), "+f"(c[1]), "+f"(c[2]), "+f"(c[3])
        : "r"(a[0]), "r"(a[1]), "r"(a[2]), "r"(a[3]), "r"(b[0]), "r"(b[1]));
}
__device__ __forceinline__ void cp16(uint32_t sa, const void* g) {
    asm volatile("cp.async.cg.shared.global [%0], [%1], 16;" :: "r"(sa), "l"(g));
}
#define CP_COMMIT() asm volatile("cp.async.commit_group;" ::: "memory")
#define CP_WAIT2()  asm volatile("cp.async.wait_group 2;" ::: "memory")
#define CP_WAIT1()  asm volatile("cp.async.wait_group 1;" ::: "memory")
#define CP_WAIT0()  asm volatile("cp.async.wait_group 0;" ::: "memory")

// ---------------- split fp32 -> bf16 hi + bf16 lo (batched) -----------------
__device__ __forceinline__ void split_body(const float* __restrict__ s,
                                           bf16* __restrict__ hi, bf16* __restrict__ lo)
{
    int i = (blockIdx.x * 256 + threadIdx.x) * 4;
    float4 v = *(const float4*)&s[i];
    bf16 h0 = __float2bfloat16_rn(v.x), h1 = __float2bfloat16_rn(v.y);
    bf16 h2 = __float2bfloat16_rn(v.z), h3 = __float2bfloat16_rn(v.w);
    bf16 l0 = __float2bfloat16_rn(v.x - __bfloat162float(h0));
    bf16 l1 = __float2bfloat16_rn(v.y - __bfloat162float(h1));
    bf16 l2 = __float2bfloat16_rn(v.z - __bfloat162float(h2));
    bf16 l3 = __float2bfloat16_rn(v.w - __bfloat162float(h3));
    *(bf162*)&hi[i]     = bf162{h0, h1};
    *(bf162*)&hi[i + 2] = bf162{h2, h3};
    *(bf162*)&lo[i]     = bf162{l0, l1};
    *(bf162*)&lo[i + 2] = bf162{l2, l3};
}

__global__ __launch_bounds__(256) void split3_kernel(
    const float* s0, const float* s1, const float* s2,
    bf16* h0, bf16* l0, bf16* h1, bf16* l1, bf16* h2, bf16* l2)
{
    const float* s = (blockIdx.y == 0) ? s0 : (blockIdx.y == 1) ? s1 : s2;
    bf16* hp = (blockIdx.y == 0) ? h0 : (blockIdx.y == 1) ? h1 : h2;
    bf16* lp = (blockIdx.y == 0) ? l0 : (blockIdx.y == 1) ? l1 : l2;
    split_body(s, hp, lp);
}

__global__ __launch_bounds__(256) void split4_kernel(
    const float* s0, const float* s1, const float* s2, const float* s3,
    bf16* h0, bf16* l0, bf16* h1, bf16* l1,
    bf16* h2, bf16* l2, bf16* h3, bf16* l3)
{
    const float* s = (blockIdx.y == 0) ? s0 : (blockIdx.y == 1) ? s1 :
                     (blockIdx.y == 2) ? s2 : s3;
    bf16* hp = (blockIdx.y == 0) ? h0 : (blockIdx.y == 1) ? h1 :
               (blockIdx.y == 2) ? h2 : h3;
    bf16* lp = (blockIdx.y == 0) ? l0 : (blockIdx.y == 1) ? l1 :
               (blockIdx.y == 2) ? l2 : l3;
    split_body(s, hp, lp);
}

// ---------------- Y = X @ W^T + bias (split-bf16, cp.async 3-stage) ---------
// Block 128(m) x 64(n), BK=32, 8 warps (warp tile 32x32). 2 CTAs/SM.
struct MMJob {
    const bf16 *Xh, *Xl, *Wh, *Wl;
    const float* bias;
    float* Yf;
    void *Yh, *Yl;      // bf16* or __half* depending on f16 flag
    int f16;
};

#define MMST 40
#define MM_XH 0
#define MM_XL (128 * MMST)
#define MM_WH (256 * MMST)
#define MM_WL (320 * MMST)
#define MM_STAGE (384 * MMST)
#define MM_SMEM  (3 * MM_STAGE * 2)      // 92160 bytes

__global__ __launch_bounds__(256, 2) void mm_bias_kernel(MMJob j0, MMJob j1, MMJob j2)
{
    extern __shared__ bf16 mms[];
    const MMJob j = (blockIdx.z == 0) ? j0 : (blockIdx.z == 1) ? j1 : j2;
    const bf16* __restrict__ Xh = j.Xh;
    const bf16* __restrict__ Xl = j.Xl;
    const bf16* __restrict__ Wh = j.Wh;
    const bf16* __restrict__ Wl = j.Wl;

    const int tid = threadIdx.x, lane = tid & 31, warp = tid >> 5;
    const int wm = warp & 3, wn = warp >> 2;
    const int m0 = blockIdx.y * 128, n0 = blockIdx.x * 64;
    const int xr = tid >> 2, xc = (tid & 3) * 8;

    #define MM_LOAD(kt, s)                                                        \
        { bf16* st = mms + (s) * MM_STAGE;                                        \
          cp16(smem_u32(&st[MM_XH + xr * MMST + xc]),                             \
               &Xh[(size_t)(m0 + xr) * ND + (kt) + xc]);                          \
          cp16(smem_u32(&st[MM_XH + (xr + 64) * MMST + xc]),                      \
               &Xh[(size_t)(m0 + xr + 64) * ND + (kt) + xc]);                     \
          cp16(smem_u32(&st[MM_XL + xr * MMST + xc]),                             \
               &Xl[(size_t)(m0 + xr) * ND + (kt) + xc]);                          \
          cp16(smem_u32(&st[MM_XL + (xr + 64) * MMST + xc]),                      \
               &Xl[(size_t)(m0 + xr + 64) * ND + (kt) + xc]);                     \
          cp16(smem_u32(&st[MM_WH + xr * MMST + xc]),                             \
               &Wh[(size_t)(n0 + xr) * ND + (kt) + xc]);                          \
          cp16(smem_u32(&st[MM_WL + xr * MMST + xc]),                             \
               &Wl[(size_t)(n0 + xr) * ND + (kt) + xc]);                          \
          CP_COMMIT(); }

    float acc[2][4][4] = {};
    MM_LOAD(0, 0);
    MM_LOAD(32, 1);
    int s = 0;
    for (int kt = 0; kt < ND; kt += 32) {
        if (kt + 64 < ND) {
            int sn = s + 2; if (sn >= 3) sn -= 3;
            MM_LOAD(kt + 64, sn);
            CP_WAIT2();
        } else if (kt + 32 < ND) {
            CP_WAIT1();
        } else {
            CP_WAIT0();
        }
        __syncthreads();
        bf16* st = mms + s * MM_STAGE;
        #pragma unroll
        for (int kk = 0; kk < 32; kk += 16) {
            uint32_t Ah[2][4], Al[2][4];
            int arow = wm * 32 + (lane & 7) + ((lane >> 3) & 1) * 8;
            int acol = kk + (lane >> 4) * 8;
            ldsm4(Ah[0], smem_u32(&st[MM_XH + arow * MMST + acol]));
            ldsm4(Ah[1], smem_u32(&st[MM_XH + (arow + 16) * MMST + acol]));
            ldsm4(Al[0], smem_u32(&st[MM_XL + arow * MMST + acol]));
            ldsm4(Al[1], smem_u32(&st[MM_XL + (arow + 16) * MMST + acol]));
            #pragma unroll
            for (int nt2 = 0; nt2 < 2; nt2++) {
                uint32_t Bh[4], Bl[4];
                int brow = wn * 32 + nt2 * 16 + (lane >> 4) * 8 + (lane & 7);
                int bcol = kk + ((lane >> 3) & 1) * 8;
                ldsm4(Bh, smem_u32(&st[MM_WH + brow * MMST + bcol]));
                ldsm4(Bl, smem_u32(&st[MM_WL + brow * MMST + bcol]));
                #pragma unroll
                for (int mt = 0; mt < 2; mt++)
                    #pragma unroll
                    for (int p = 0; p < 2; p++) {
                        mma16816(acc[mt][nt2 * 2 + p], Ah[mt], &Bh[p * 2]);
                        mma16816(acc[mt][nt2 * 2 + p], Ah[mt], &Bl[p * 2]);
                        mma16816(acc[mt][nt2 * 2 + p], Al[mt], &Bh[p * 2]);
                    }
            }
        }
        __syncthreads();
        s = (s + 1 >= 3) ? 0 : s + 1;
    }

    const int r0 = lane >> 2, cc = (lane & 3) * 2;
    #pragma unroll
    for (int mt = 0; mt < 2; mt++)
        #pragma unroll
        for (int nt = 0; nt < 4; nt++) {
            int m = m0 + wm * 32 + mt * 16 + r0;
            int n = n0 + wn * 32 + nt * 8 + cc;
            float b0 = j.bias[n], b1 = j.bias[n + 1];
            float v0 = acc[mt][nt][0] + b0, v1 = acc[mt][nt][1] + b1;
            float v2 = acc[mt][nt][2] + b0, v3 = acc[mt][nt][3] + b1;
            if (j.Yf) {
                *(float2*)&j.Yf[(size_t)m * ND + n]       = float2{v0, v1};
                *(float2*)&j.Yf[(size_t)(m + 8) * ND + n] = float2{v2, v3};
            }
            if (j.Yh) {
                if (j.f16) {
                    __half* Yh = (__half*)j.Yh;
                    __half* Yl = (__half*)j.Yl;
                    __half h0 = __float2half_rn(v0), h1 = __float2half_rn(v1);
                    __half h2 = __float2half_rn(v2), h3 = __float2half_rn(v3);
                    *(__half2*)&Yh[(size_t)m * ND + n]       = __halves2half2(h0, h1);
                    *(__half2*)&Yh[(size_t)(m + 8) * ND + n] = __halves2half2(h2, h3);
                    *(__half2*)&Yl[(size_t)m * ND + n] =
                        __halves2half2(__float2half_rn(v0 - __half2float(h0)),
                                       __float2half_rn(v1 - __half2float(h1)));
                    *(__half2*)&Yl[(size_t)(m + 8) * ND + n] =
                        __halves2half2(__float2half_rn(v2 - __half2float(h2)),
                                       __float2half_rn(v3 - __half2float(h3)));
                } else {
                    bf16* Yh = (bf16*)j.Yh;
                    bf16* Yl = (bf16*)j.Yl;
                    bf16 h0 = __float2bfloat16_rn(v0), h1 = __float2bfloat16_rn(v1);
                    bf16 h2 = __float2bfloat16_rn(v2), h3 = __float2bfloat16_rn(v3);
                    *(bf162*)&Yh[(size_t)m * ND + n]       = bf162{h0, h1};
                    *(bf162*)&Yh[(size_t)(m + 8) * ND + n] = bf162{h2, h3};
                    *(bf162*)&Yl[(size_t)m * ND + n] =
                        bf162{__float2bfloat16_rn(v0 - __bfloat162float(h0)),
                              __float2bfloat16_rn(v1 - __bfloat162float(h1))};
                    *(bf162*)&Yl[(size_t)(m + 8) * ND + n] =
                        bf162{__float2bfloat16_rn(v2 - __bfloat162float(h2)),
                              __float2bfloat16_rn(v3 - __bfloat162float(h3))};
                }
            }
        }
}

// ---------------- logits = 0.125 * Q K^T (per head), fp16 output ------------
#define QKS 72
#define QK_QH 0
#define QK_QL (QK_QH + 128 * QKS * 2)
#define QK_KH (QK_QL + 128 * QKS * 2)
#define QK_KL (QK_KH + 128 * QKS * 2)
#define QK_SMEM (QK_KL + 128 * QKS * 2)

__global__ __launch_bounds__(256) void qk_kernel()
{
    extern __shared__ char sm[];
    bf16* Qsh = (bf16*)(sm + QK_QH);
    bf16* Qsl = (bf16*)(sm + QK_QL);
    bf16* Ksh = (bf16*)(sm + QK_KH);
    bf16* Ksl = (bf16*)(sm + QK_KL);

    const int tid = threadIdx.x, lane = tid & 31, warp = tid >> 5;
    const int wm = warp & 3, wn = warp >> 2;
    const int h = blockIdx.z;
    const int q0 = blockIdx.y * 128, k0 = blockIdx.x * 128;
    const int ho = h * DH;

    const int lr = tid >> 2, lc = (tid & 3) * 16;
    #pragma unroll
    for (int it = 0; it < 2; it++) {
        int r = lr + it * 64;
        *(uint4*)&Qsh[r * QKS + lc]     = *(const uint4*)&g_Qh[(size_t)(q0 + r) * ND + ho + lc];
        *(uint4*)&Qsh[r * QKS + lc + 8] = *(const uint4*)&g_Qh[(size_t)(q0 + r) * ND + ho + lc + 8];
        *(uint4*)&Qsl[r * QKS + lc]     = *(const uint4*)&g_Ql[(size_t)(q0 + r) * ND + ho + lc];
        *(uint4*)&Qsl[r * QKS + lc + 8] = *(const uint4*)&g_Ql[(size_t)(q0 + r) * ND + ho + lc + 8];
        *(uint4*)&Ksh[r * QKS + lc]     = *(const uint4*)&g_Kh[(size_t)(k0 + r) * ND + ho + lc];
        *(uint4*)&Ksh[r * QKS + lc + 8] = *(const uint4*)&g_Kh[(size_t)(k0 + r) * ND + ho + lc + 8];
        *(uint4*)&Ksl[r * QKS + lc]     = *(const uint4*)&g_Kl[(size_t)(k0 + r) * ND + ho + lc];
        *(uint4*)&Ksl[r * QKS + lc + 8] = *(const uint4*)&g_Kl[(size_t)(k0 + r) * ND + ho + lc + 8];
    }
    __syncthreads();

    float acc[2][8][4] = {};
    #pragma unroll
    for (int kk = 0; kk < 64; kk += 16) {
        uint32_t Ah[2][4], Al[2][4];
        int arow = wm * 32 + (lane & 7) + ((lane >> 3) & 1) * 8;
        int acol = kk + (lane >> 4) * 8;
        ldsm4(Ah[0], smem_u32(&Qsh[arow * QKS + acol]));
        ldsm4(Ah[1], smem_u32(&Qsh[(arow + 16) * QKS + acol]));
        ldsm4(Al[0], smem_u32(&Qsl[arow * QKS + acol]));
        ldsm4(Al[1], smem_u32(&Qsl[(arow + 16) * QKS + acol]));
        #pragma unroll
        for (int nt2 = 0; nt2 < 4; nt2++) {
            uint32_t Bh[4], Bl[4];
            int brow = wn * 64 + nt2 * 16 + (lane >> 4) * 8 + (lane & 7);
            int bcol = kk + ((lane >> 3) & 1) * 8;
            ldsm4(Bh, smem_u32(&Ksh[brow * QKS + bcol]));
            ldsm4(Bl, smem_u32(&Ksl[brow * QKS + bcol]));
            #pragma unroll
            for (int mt = 0; mt < 2; mt++)
                #pragma unroll
                for (int p = 0; p < 2; p++) {
                    mma16816(acc[mt][nt2 * 2 + p], Ah[mt], &Bh[p * 2]);
                    mma16816(acc[mt][nt2 * 2 + p], Ah[mt], &Bl[p * 2]);
                    mma16816(acc[mt][nt2 * 2 + p], Al[mt], &Bh[p * 2]);
                }
        }
    }

    __half* out = g_logith + (size_t)h * SEQ * SEQ;
    const int r0 = lane >> 2, cc = (lane & 3) * 2;
    #pragma unroll
    for (int mt = 0; mt < 2; mt++)
        #pragma unroll
        for (int nt = 0; nt < 8; nt++) {
            int m = q0 + wm * 32 + mt * 16 + r0;
            int n = k0 + wn * 64 + nt * 8 + cc;
            *(__half2*)&out[(size_t)m * SEQ + n] =
                __floats2half2_rn(acc[mt][nt][0] * 0.125f, acc[mt][nt][1] * 0.125f);
            *(__half2*)&out[(size_t)(m + 8) * SEQ + n] =
                __floats2half2_rn(acc[mt][nt][2] * 0.125f, acc[mt][nt][3] * 0.125f);
        }
}

// -------- li[h,q,n] = sum_d Q[q, h*64+d] * pos_emb[d, n] --------------------
__global__ __launch_bounds__(256) void li_kernel(const float* __restrict__ pos_emb)
{
    __shared__ float Qs[64][65];
    __shared__ float Ps[64][65];
    const int tid = threadIdx.x;
    const int tx = tid & 15, ty = tid >> 4;
    const int h = blockIdx.y;
    const int q0 = blockIdx.x * 64;

    for (int i = tid; i < 64 * 64; i += 256) {
        int r = i >> 6, c = i & 63;
        Qs[r][c] = g_Q[(q0 + r) * ND + h * DH + c];
        Ps[r][c] = pos_emb[r * NPOS + c];
    }
    __syncthreads();

    float acc[4][4] = {};
    #pragma unroll 8
    for (int d = 0; d < 64; d++) {
        float a[4], b[4];
        #pragma unroll
        for (int i = 0; i < 4; i++) a[i] = Qs[ty * 4 + i][d];
        #pragma unroll
        for (int j = 0; j < 4; j++) b[j] = Ps[d][tx * 4 + j];
        #pragma unroll
        for (int i = 0; i < 4; i++)
            #pragma unroll
            for (int j = 0; j < 4; j++) acc[i][j] += a[i] * b[j];
    }
    #pragma unroll
    for (int i = 0; i < 4; i++)
        #pragma unroll
        for (int j = 0; j < 4; j++)
            g_li[(h * SEQ + q0 + ty * 4 + i) * NPOS + tx * 4 + j] = acc[i][j];
}

// -------- per (h,q) row: gates -> suffix-cumsum -> CoPE -> softmax ----------
// Reads fp16 logits; writes scores as ONE fp16 array.
__global__ __launch_bounds__(256) void cope_softmax_kernel()
{
    __shared__ float li[NPOS];
    __shared__ float wsum[8];
    __shared__ float redm[8];
    __shared__ float reds[8];

    const int tid = threadIdx.x;
    const int lane = tid & 31, warp = tid >> 5;
    const int q = blockIdx.x, h = blockIdx.y;
    const size_t rbase = ((size_t)h * SEQ + q) * SEQ;
    const __half* lrow = g_logith + rbase;

    if (tid < NPOS) li[tid] = g_li[(h * SEQ + q) * NPOS + tid];

    const int base = tid * 8;
    uint4 raw = *(const uint4*)&lrow[base];
    const __half2* hp = (const __half2*)&raw;
    float x[8];
    {
        float2 f0 = __half22float2(hp[0]);
        float2 f1 = __half22float2(hp[1]);
        float2 f2 = __half22float2(hp[2]);
        float2 f3 = __half22float2(hp[3]);
        x[0] = f0.x; x[1] = f0.y; x[2] = f1.x; x[3] = f1.y;
        x[4] = f2.x; x[5] = f2.y; x[6] = f3.x; x[7] = f3.y;
    }

    float g[8];
    float csum = 0.0f;
    #pragma unroll
    for (int j = 7; j >= 0; --j) {
        float t;
        asm("tanh.approx.f32 %0, %1;" : "=f"(t) : "f"(x[j] * 0.5f));
        csum += fmaf(t, 0.5f, 0.5f);
        g[j] = csum;
    }
    float v = csum;
    #pragma unroll
    for (int d = 1; d < 32; d <<= 1) {
        float n = __shfl_up_sync(0xffffffffu, v, d);
        if (lane >= d) v += n;
    }
    if (lane == 31) wsum[warp] = v;
    __syncthreads();
    float wpre = 0.0f, total = 0.0f;
    #pragma unroll
    for (int w = 0; w < 8; w++) {
        float s = wsum[w];
        if (w < warp) wpre += s;
        total += s;
    }
    const float off = total - (wpre + v);

    float lmax = -INFINITY;
    #pragma unroll
    for (int j = 0; j < 8; j++) {
        float pos = fminf(g[j] + off, (float)(NPOS - 1));
        float pf = floorf(pos);
        int fi = (int)pf;
        int ci = (int)ceilf(pos);
        float w = pos - pf;
        x[j] += li[ci] * w + li[fi] * (1.0f - w);
        lmax = fmaxf(lmax, x[j]);
    }
    #pragma unroll
    for (int d = 16; d > 0; d >>= 1)
        lmax = fmaxf(lmax, __shfl_xor_sync(0xffffffffu, lmax, d));
    if (lane == 0) redm[warp] = lmax;
    __syncthreads();
    float mx = redm[0];
    #pragma unroll
    for (int w = 1; w < 8; w++) mx = fmaxf(mx, redm[w]);

    float lsum = 0.0f;
    #pragma unroll
    for (int j = 0; j < 8; j++) {
        x[j] = __expf(x[j] - mx);
        lsum += x[j];
    }
    #pragma unroll
    for (int d = 16; d > 0; d >>= 1)
        lsum += __shfl_xor_sync(0xffffffffu, lsum, d);
    if (lane == 0) reds[warp] = lsum;
    __syncthreads();
    float tsum = 0.0f;
    #pragma unroll
    for (int w = 0; w < 8; w++) tsum += reds[w];
    const float inv = 1.0f / tsum;

    __half hs[8];
    #pragma unroll
    for (int j = 0; j < 8; j++) hs[j] = __float2half_rn(x[j] * inv);
    *(uint4*)&g_Sf[rbase + base] = *(uint4*)hs;
}

// -------- ctx = S(fp16) @ V(fp16 hi/lo), cp.async 3-stage -------------------
// Block 128(q) x 64(n=head), BK=32, 8 warps (32x32). 2 CTAs/SM. 2 MMA terms.
#define CXST  40
#define CXVST 72
#define CX_S  0
#define CX_VH (128 * CXST)
#define CX_VL (128 * CXST + 32 * CXVST)
#define CX_STAGE (128 * CXST + 64 * CXVST)   // 9728 halves (19456 B)
#define CX_SMEM  (3 * CX_STAGE * 2)          // 58368 bytes

__global__ __launch_bounds__(256, 2) void ctx_kernel()
{
    extern __shared__ __half cxs[];
    const int tid = threadIdx.x, lane = tid & 31, warp = tid >> 5;
    const int wm = warp & 3, wn = warp >> 2;
    const int h = blockIdx.y;
    const int q0 = blockIdx.x * 128;
    const int ho = h * DH;
    const __half* Sf = g_Sf + (size_t)h * SEQ * SEQ;

    const int sr = tid >> 1, sc = (tid & 1) * 16;
    const int vr = tid >> 3, vc = (tid & 7) * 8;

    #define CX_LOAD(kt, s)                                                        \
        { __half* st = cxs + (s) * CX_STAGE;                                      \
          cp16(smem_u32(&st[CX_S + sr * CXST + sc]),                              \
               &Sf[(size_t)(q0 + sr) * SEQ + (kt) + sc]);                         \
          cp16(smem_u32(&st[CX_S + sr * CXST + sc + 8]),                          \
               &Sf[(size_t)(q0 + sr) * SEQ + (kt) + sc + 8]);                     \
          cp16(smem_u32(&st[CX_VH + vr * CXVST + vc]),                            \
               &g_Vh[(size_t)((kt) + vr) * ND + ho + vc]);                        \
          cp16(smem_u32(&st[CX_VL + vr * CXVST + vc]),                            \
               &g_Vl[(size_t)((kt) + vr) * ND + ho + vc]);                        \
          CP_COMMIT(); }

    float acc[2][4][4] = {};
    CX_LOAD(0, 0);
    CX_LOAD(32, 1);
    int s = 0;
    for (int kt = 0; kt < SEQ; kt += 32) {
        if (kt + 64 < SEQ) {
            int sn = s + 2; if (sn >= 3) sn -= 3;
            CX_LOAD(kt + 64, sn);
            CP_WAIT2();
        } else if (kt + 32 < SEQ) {
            CP_WAIT1();
        } else {
            CP_WAIT0();
        }
        __syncthreads();
        __half* st = cxs + s * CX_STAGE;
        #pragma unroll
        for (int kk = 0; kk < 32; kk += 16) {
            uint32_t A[2][4];
            int arow = wm * 32 + (lane & 7) + ((lane >> 3) & 1) * 8;
            int acol = kk + (lane >> 4) * 8;
            ldsm4(A[0], smem_u32(&st[CX_S + arow * CXST + acol]));
            ldsm4(A[1], smem_u32(&st[CX_S + (arow + 16) * CXST + acol]));
            #pragma unroll
            for (int nt2 = 0; nt2 < 2; nt2++) {
                uint32_t Bh[4], Bl[4];
                int vrow = kk + ((lane >> 3) & 1) * 8 + (lane & 7);
                int vcol = wn * 32 + nt2 * 16 + (lane >> 4) * 8;
                ldsm4t(Bh, smem_u32(&st[CX_VH + vrow * CXVST + vcol]));
                ldsm4t(Bl, smem_u32(&st[CX_VL + vrow * CXVST + vcol]));
                #pragma unroll
                for (int mt = 0; mt < 2; mt++)
                    #pragma unroll
                    for (int p = 0; p < 2; p++) {
                        mma16816h(acc[mt][nt2 * 2 + p], A[mt], &Bh[p * 2]);
                        mma16816h(acc[mt][nt2 * 2 + p], A[mt], &Bl[p * 2]);
                    }
            }
        }
        __syncthreads();
        s = (s + 1 >= 3) ? 0 : s + 1;
    }

    const int r0 = lane >> 2, cc = (lane & 3) * 2;
    #pragma unroll
    for (int mt = 0; mt < 2; mt++)
        #pragma unroll
        for (int nt = 0; nt < 4; nt++) {
            int m = q0 + wm * 32 + mt * 16 + r0;
            int n = ho + wn * 32 + nt * 8 + cc;
            float v0 = acc[mt][nt][0], v1 = acc[mt][nt][1];
            float v2 = acc[mt][nt][2], v3 = acc[mt][nt][3];
            bf16 h0 = __float2bfloat16_rn(v0), h1 = __float2bfloat16_rn(v1);
            bf16 h2 = __float2bfloat16_rn(v2), h3 = __float2bfloat16_rn(v3);
            *(bf162*)&g_ctxh[(size_t)m * ND + n]       = bf162{h0, h1};
            *(bf162*)&g_ctxh[(size_t)(m + 8) * ND + n] = bf162{h2, h3};
            *(bf162*)&g_ctxl[(size_t)m * ND + n] =
                bf162{__float2bfloat16_rn(v0 - __bfloat162float(h0)),
                      __float2bfloat16_rn(v1 - __bfloat162float(h1))};
            *(bf162*)&g_ctxl[(size_t)(m + 8) * ND + n] =
                bf162{__float2bfloat16_rn(v2 - __bfloat162float(h2)),
                      __float2bfloat16_rn(v3 - __bfloat162float(h3))};
        }
}

// ---------------------------------------------------------------------------
extern "C" void kernel_launch(void* const* d_in, const int* in_sizes, int n_in,
                              void* d_out, int out_size)
{
    const float* q      = (const float*)d_in[0];
    const float* k      = (const float*)d_in[1];
    const float* v      = (const float*)d_in[2];
    const float* Wq_w   = (const float*)d_in[3];
    const float* Wq_b   = (const float*)d_in[4];
    const float* Wk_w   = (const float*)d_in[5];
    const float* Wk_b   = (const float*)d_in[6];
    const float* Wv_w   = (const float*)d_in[7];
    const float* Wv_b   = (const float*)d_in[8];
    const float* Wo_w   = (const float*)d_in[9];
    const float* Wo_b   = (const float*)d_in[10];
    const float* pos_emb= (const float*)d_in[11];
    float* out = (float*)d_out;

    static bool attr_set = false;
    if (!attr_set) {
        cudaFuncSetAttribute(mm_bias_kernel,
                             cudaFuncAttributeMaxDynamicSharedMemorySize, MM_SMEM);
        cudaFuncSetAttribute(qk_kernel,
                             cudaFuncAttributeMaxDynamicSharedMemorySize, QK_SMEM);
        cudaFuncSetAttribute(ctx_kernel,
                             cudaFuncAttributeMaxDynamicSharedMemorySize, CX_SMEM);
        attr_set = true;
    }

    bf16 *inqh, *inql, *inkh, *inkl, *invh, *invl;
    bf16 *wqh, *wql, *wkh, *wkl, *wvh, *wvl, *woh, *wol;
    bf16 *Qh, *Ql, *Kh, *Kl, *ctxh, *ctxl;
    __half *Vh, *Vl;
    float* Qf;
    cudaGetSymbolAddress((void**)&inqh, g_inqh); cudaGetSymbolAddress((void**)&inql, g_inql);
    cudaGetSymbolAddress((void**)&inkh, g_inkh); cudaGetSymbolAddress((void**)&inkl, g_inkl);
    cudaGetSymbolAddress((void**)&invh, g_invh); cudaGetSymbolAddress((void**)&invl, g_invl);
    cudaGetSymbolAddress((void**)&wqh, g_wqh);   cudaGetSymbolAddress((void**)&wql, g_wql);
    cudaGetSymbolAddress((void**)&wkh, g_wkh);   cudaGetSymbolAddress((void**)&wkl, g_wkl);
    cudaGetSymbolAddress((void**)&wvh, g_wvh);   cudaGetSymbolAddress((void**)&wvl, g_wvl);
    cudaGetSymbolAddress((void**)&woh, g_woh);   cudaGetSymbolAddress((void**)&wol, g_wol);
    cudaGetSymbolAddress((void**)&Qh, g_Qh);     cudaGetSymbolAddress((void**)&Ql, g_Ql);
    cudaGetSymbolAddress((void**)&Kh, g_Kh);     cudaGetSymbolAddress((void**)&Kl, g_Kl);
    cudaGetSymbolAddress((void**)&Vh, g_Vh);     cudaGetSymbolAddress((void**)&Vl, g_Vl);
    cudaGetSymbolAddress((void**)&ctxh, g_ctxh); cudaGetSymbolAddress((void**)&ctxl, g_ctxl);
    cudaGetSymbolAddress((void**)&Qf, g_Q);

    const int nIn = SEQ * ND / 1024;
    const int nW  = ND * ND / 1024;

    split3_kernel<<<dim3(nIn, 3), 256>>>(q, k, v,
                                         inqh, inql, inkh, inkl, invh, invl);
    split4_kernel<<<dim3(nW, 4), 256>>>(Wq_w, Wk_w, Wv_w, Wo_w,
                                        wqh, wql, wkh, wkl, wvh, wvl, woh, wol);

    MMJob jq{inqh, inql, wqh, wql, Wq_b, Qf, Qh, Ql, 0};
    MMJob jk{inkh, inkl, wkh, wkl, Wk_b, nullptr, Kh, Kl, 0};
    MMJob jv{invh, invl, wvh, wvl, Wv_b, nullptr, Vh, Vl, 1};
    MMJob jo{ctxh, ctxl, woh, wol, Wo_b, out, nullptr, nullptr, 0};

    dim3 gProj3(ND / 64, SEQ / 128, 3);   // 768 CTAs
    mm_bias_kernel<<<gProj3, 256, MM_SMEM>>>(jq, jk, jv);

    qk_kernel<<<dim3(SEQ / 128, SEQ / 128, NH), 256, QK_SMEM>>>();
    li_kernel<<<dim3(SEQ / 64, NH), 256>>>(pos_emb);
    cope_softmax_kernel<<<dim3(SEQ, NH), 256>>>();
    ctx_kernel<<<dim3(SEQ / 128, NH), 256, CX_SMEM>>>();

    dim3 gProj1(ND / 64, SEQ / 128, 1);
    mm_bias_kernel<<<gProj1, 256, MM_SMEM>>>(jo, jo, jo);
}

// round 17
// speedup vs baseline: 1.6262x; 1.0653x over previous
#include <cuda_runtime.h>
#include <cuda_bf16.h>
#include <cuda_fp16.h>
#include <math.h>
#include <stdint.h>

#define SEQ   2048
#define ND    1024
#define NH    16
#define DH    64
#define NPOS  64

typedef __nv_bfloat16 bf16;
typedef __nv_bfloat162 bf162;

// ---------------- scratch (device globals: allocation-free) ----------------
__device__ float g_Q[SEQ * ND];
__device__ __half g_logith[(size_t)NH * SEQ * SEQ];   // 128 MB fp16 logits
__device__ float g_li[NH * SEQ * NPOS];

__device__ bf16 g_inqh[SEQ * ND], g_inql[SEQ * ND];
__device__ bf16 g_inkh[SEQ * ND], g_inkl[SEQ * ND];
__device__ bf16 g_invh[SEQ * ND], g_invl[SEQ * ND];
__device__ bf16 g_wqh[ND * ND], g_wql[ND * ND];
__device__ bf16 g_wkh[ND * ND], g_wkl[ND * ND];
__device__ bf16 g_wvh[ND * ND], g_wvl[ND * ND];
__device__ bf16 g_woh[ND * ND], g_wol[ND * ND];
__device__ __half g_Qh[SEQ * ND], g_Ql[SEQ * ND];     // Q fp16 (qk uses hi only)
__device__ __half g_Kh[SEQ * ND], g_Kl[SEQ * ND];     // K fp16 (qk uses hi only)
__device__ __half g_Vh[SEQ * ND], g_Vl[SEQ * ND];     // V split in fp16
__device__ bf16 g_ctxh[SEQ * ND], g_ctxl[SEQ * ND];
__device__ __half g_Sf[(size_t)NH * SEQ * SEQ];       // scores fp16 (134 MB)

// ---------------- PTX helpers ----------------------------------------------
__device__ __forceinline__ uint32_t smem_u32(const void* p) {
    return (uint32_t)__cvta_generic_to_shared(p);
}
__device__ __forceinline__ void ldsm4(uint32_t* r, uint32_t a) {
    asm volatile("ldmatrix.sync.aligned.m8n8.x4.shared.b16 {%0,%1,%2,%3}, [%4];"
                 : "=r"(r[0]), "=r"(r[1]), "=r"(r[2]), "=r"(r[3]) : "r"(a));
}
__device__ __forceinline__ void ldsm4t(uint32_t* r, uint32_t a) {
    asm volatile("ldmatrix.sync.aligned.m8n8.x4.trans.shared.b16 {%0,%1,%2,%3}, [%4];"
                 : "=r"(r[0]), "=r"(r[1]), "=r"(r[2]), "=r"(r[3]) : "r"(a));
}
__device__ __forceinline__ void mma16816(float* c, const uint32_t* a, const uint32_t* b) {
    asm volatile(
        "mma.sync.aligned.m16n8k16.row.col.f32.bf16.bf16.f32 "
        "{%0,%1,%2,%3}, {%4,%5,%6,%7}, {%8,%9}, {%0,%1,%2,%3};"
        : "+f"(c[0]), "+f"(c[1]), "+f"(c[2]), "+f"(c[3])
        : "r"(a[0]), "r"(a[1]), "r"(a[2]), "r"(a[3]), "r"(b[0]), "r"(b[1]));
}
__device__ __forceinline__ void mma16816h(float* c, const uint32_t* a, const uint32_t* b) {
    asm volatile(
        "mma.sync.aligned.m16n8k16.row.col.f32.f16.f16.f32 "
        "{%0,%1,%2,%3}, {%4,%5,%6,%7}, {%8,%9}, {%0,%1,%2,%3};"
        : "+f"(c[0]), "+f"(c[1]), "+f"(c[2]), "+f"(c[3])
        : "r"(a[0]), "r"(a[1]), "r"(a[2]), "r"(a[3]), "r"(b[0]), "r"(b[1]));
}
__device__ __forceinline__ void cp16(uint32_t sa, const void* g) {
    asm volatile("cp.async.cg.shared.global [%0], [%1], 16;" :: "r"(sa), "l"(g));
}
#define CP_COMMIT() asm volatile("cp.async.commit_group;" ::: "memory")
#define CP_WAIT2()  asm volatile("cp.async.wait_group 2;" ::: "memory")
#define CP_WAIT1()  asm volatile("cp.async.wait_group 1;" ::: "memory")
#define CP_WAIT0()  asm volatile("cp.async.wait_group 0;" ::: "memory")

// ---------------- split fp32 -> bf16 hi + bf16 lo (batched) -----------------
__device__ __forceinline__ void split_body(const float* __restrict__ s,
                                           bf16* __restrict__ hi, bf16* __restrict__ lo)
{
    int i = (blockIdx.x * 256 + threadIdx.x) * 4;
    float4 v = *(const float4*)&s[i];
    bf16 h0 = __float2bfloat16_rn(v.x), h1 = __float2bfloat16_rn(v.y);
    bf16 h2 = __float2bfloat16_rn(v.z), h3 = __float2bfloat16_rn(v.w);
    bf16 l0 = __float2bfloat16_rn(v.x - __bfloat162float(h0));
    bf16 l1 = __float2bfloat16_rn(v.y - __bfloat162float(h1));
    bf16 l2 = __float2bfloat16_rn(v.z - __bfloat162float(h2));
    bf16 l3 = __float2bfloat16_rn(v.w - __bfloat162float(h3));
    *(bf162*)&hi[i]     = bf162{h0, h1};
    *(bf162*)&hi[i + 2] = bf162{h2, h3};
    *(bf162*)&lo[i]     = bf162{l0, l1};
    *(bf162*)&lo[i + 2] = bf162{l2, l3};
}

__global__ __launch_bounds__(256) void split3_kernel(
    const float* s0, const float* s1, const float* s2,
    bf16* h0, bf16* l0, bf16* h1, bf16* l1, bf16* h2, bf16* l2)
{
    const float* s = (blockIdx.y == 0) ? s0 : (blockIdx.y == 1) ? s1 : s2;
    bf16* hp = (blockIdx.y == 0) ? h0 : (blockIdx.y == 1) ? h1 : h2;
    bf16* lp = (blockIdx.y == 0) ? l0 : (blockIdx.y == 1) ? l1 : l2;
    split_body(s, hp, lp);
}

__global__ __launch_bounds__(256) void split4_kernel(
    const float* s0, const float* s1, const float* s2, const float* s3,
    bf16* h0, bf16* l0, bf16* h1, bf16* l1,
    bf16* h2, bf16* l2, bf16* h3, bf16* l3)
{
    const float* s = (blockIdx.y == 0) ? s0 : (blockIdx.y == 1) ? s1 :
                     (blockIdx.y == 2) ? s2 : s3;
    bf16* hp = (blockIdx.y == 0) ? h0 : (blockIdx.y == 1) ? h1 :
               (blockIdx.y == 2) ? h2 : h3;
    bf16* lp = (blockIdx.y == 0) ? l0 : (blockIdx.y == 1) ? l1 :
               (blockIdx.y == 2) ? l2 : l3;
    split_body(s, hp, lp);
}

// ---------------- Y = X @ W^T + bias (split-bf16, cp.async 3-stage) ---------
// Block 128(m) x 64(n), BK=32, 8 warps (warp tile 32x32). 2 CTAs/SM.
struct MMJob {
    const bf16 *Xh, *Xl, *Wh, *Wl;
    const float* bias;
    float* Yf;
    void *Yh, *Yl;      // bf16* or __half* depending on f16 flag
    int f16;
};

#define MMST 40
#define MM_XH 0
#define MM_XL (128 * MMST)
#define MM_WH (256 * MMST)
#define MM_WL (320 * MMST)
#define MM_STAGE (384 * MMST)
#define MM_SMEM  (3 * MM_STAGE * 2)      // 92160 bytes

__global__ __launch_bounds__(256, 2) void mm_bias_kernel(MMJob j0, MMJob j1, MMJob j2)
{
    extern __shared__ bf16 mms[];
    const MMJob j = (blockIdx.z == 0) ? j0 : (blockIdx.z == 1) ? j1 : j2;
    const bf16* __restrict__ Xh = j.Xh;
    const bf16* __restrict__ Xl = j.Xl;
    const bf16* __restrict__ Wh = j.Wh;
    const bf16* __restrict__ Wl = j.Wl;

    const int tid = threadIdx.x, lane = tid & 31, warp = tid >> 5;
    const int wm = warp & 3, wn = warp >> 2;
    const int m0 = blockIdx.y * 128, n0 = blockIdx.x * 64;
    const int xr = tid >> 2, xc = (tid & 3) * 8;

    #define MM_LOAD(kt, s)                                                        \
        { bf16* st = mms + (s) * MM_STAGE;                                        \
          cp16(smem_u32(&st[MM_XH + xr * MMST + xc]),                             \
               &Xh[(size_t)(m0 + xr) * ND + (kt) + xc]);                          \
          cp16(smem_u32(&st[MM_XH + (xr + 64) * MMST + xc]),                      \
               &Xh[(size_t)(m0 + xr + 64) * ND + (kt) + xc]);                     \
          cp16(smem_u32(&st[MM_XL + xr * MMST + xc]),                             \
               &Xl[(size_t)(m0 + xr) * ND + (kt) + xc]);                          \
          cp16(smem_u32(&st[MM_XL + (xr + 64) * MMST + xc]),                      \
               &Xl[(size_t)(m0 + xr + 64) * ND + (kt) + xc]);                     \
          cp16(smem_u32(&st[MM_WH + xr * MMST + xc]),                             \
               &Wh[(size_t)(n0 + xr) * ND + (kt) + xc]);                          \
          cp16(smem_u32(&st[MM_WL + xr * MMST + xc]),                             \
               &Wl[(size_t)(n0 + xr) * ND + (kt) + xc]);                          \
          CP_COMMIT(); }

    float acc[2][4][4] = {};
    MM_LOAD(0, 0);
    MM_LOAD(32, 1);
    int s = 0;
    for (int kt = 0; kt < ND; kt += 32) {
        if (kt + 64 < ND) {
            int sn = s + 2; if (sn >= 3) sn -= 3;
            MM_LOAD(kt + 64, sn);
            CP_WAIT2();
        } else if (kt + 32 < ND) {
            CP_WAIT1();
        } else {
            CP_WAIT0();
        }
        __syncthreads();
        bf16* st = mms + s * MM_STAGE;
        #pragma unroll
        for (int kk = 0; kk < 32; kk += 16) {
            uint32_t Ah[2][4], Al[2][4];
            int arow = wm * 32 + (lane & 7) + ((lane >> 3) & 1) * 8;
            int acol = kk + (lane >> 4) * 8;
            ldsm4(Ah[0], smem_u32(&st[MM_XH + arow * MMST + acol]));
            ldsm4(Ah[1], smem_u32(&st[MM_XH + (arow + 16) * MMST + acol]));
            ldsm4(Al[0], smem_u32(&st[MM_XL + arow * MMST + acol]));
            ldsm4(Al[1], smem_u32(&st[MM_XL + (arow + 16) * MMST + acol]));
            #pragma unroll
            for (int nt2 = 0; nt2 < 2; nt2++) {
                uint32_t Bh[4], Bl[4];
                int brow = wn * 32 + nt2 * 16 + (lane >> 4) * 8 + (lane & 7);
                int bcol = kk + ((lane >> 3) & 1) * 8;
                ldsm4(Bh, smem_u32(&st[MM_WH + brow * MMST + bcol]));
                ldsm4(Bl, smem_u32(&st[MM_WL + brow * MMST + bcol]));
                #pragma unroll
                for (int mt = 0; mt < 2; mt++)
                    #pragma unroll
                    for (int p = 0; p < 2; p++) {
                        mma16816(acc[mt][nt2 * 2 + p], Ah[mt], &Bh[p * 2]);
                        mma16816(acc[mt][nt2 * 2 + p], Ah[mt], &Bl[p * 2]);
                        mma16816(acc[mt][nt2 * 2 + p], Al[mt], &Bh[p * 2]);
                    }
            }
        }
        __syncthreads();
        s = (s + 1 >= 3) ? 0 : s + 1;
    }

    const int r0 = lane >> 2, cc = (lane & 3) * 2;
    #pragma unroll
    for (int mt = 0; mt < 2; mt++)
        #pragma unroll
        for (int nt = 0; nt < 4; nt++) {
            int m = m0 + wm * 32 + mt * 16 + r0;
            int n = n0 + wn * 32 + nt * 8 + cc;
            float b0 = j.bias[n], b1 = j.bias[n + 1];
            float v0 = acc[mt][nt][0] + b0, v1 = acc[mt][nt][1] + b1;
            float v2 = acc[mt][nt][2] + b0, v3 = acc[mt][nt][3] + b1;
            if (j.Yf) {
                *(float2*)&j.Yf[(size_t)m * ND + n]       = float2{v0, v1};
                *(float2*)&j.Yf[(size_t)(m + 8) * ND + n] = float2{v2, v3};
            }
            if (j.Yh) {
                if (j.f16) {
                    __half* Yh = (__half*)j.Yh;
                    __half* Yl = (__half*)j.Yl;
                    __half h0 = __float2half_rn(v0), h1 = __float2half_rn(v1);
                    __half h2 = __float2half_rn(v2), h3 = __float2half_rn(v3);
                    *(__half2*)&Yh[(size_t)m * ND + n]       = __halves2half2(h0, h1);
                    *(__half2*)&Yh[(size_t)(m + 8) * ND + n] = __halves2half2(h2, h3);
                    *(__half2*)&Yl[(size_t)m * ND + n] =
                        __halves2half2(__float2half_rn(v0 - __half2float(h0)),
                                       __float2half_rn(v1 - __half2float(h1)));
                    *(__half2*)&Yl[(size_t)(m + 8) * ND + n] =
                        __halves2half2(__float2half_rn(v2 - __half2float(h2)),
                                       __float2half_rn(v3 - __half2float(h3)));
                } else {
                    bf16* Yh = (bf16*)j.Yh;
                    bf16* Yl = (bf16*)j.Yl;
                    bf16 h0 = __float2bfloat16_rn(v0), h1 = __float2bfloat16_rn(v1);
                    bf16 h2 = __float2bfloat16_rn(v2), h3 = __float2bfloat16_rn(v3);
                    *(bf162*)&Yh[(size_t)m * ND + n]       = bf162{h0, h1};
                    *(bf162*)&Yh[(size_t)(m + 8) * ND + n] = bf162{h2, h3};
                    *(bf162*)&Yl[(size_t)m * ND + n] =
                        bf162{__float2bfloat16_rn(v0 - __bfloat162float(h0)),
                              __float2bfloat16_rn(v1 - __bfloat162float(h1))};
                    *(bf162*)&Yl[(size_t)(m + 8) * ND + n] =
                        bf162{__float2bfloat16_rn(v2 - __bfloat162float(h2)),
                              __float2bfloat16_rn(v3 - __bfloat162float(h3))};
                }
            }
        }
}

// ---------------- logits = 0.125 * Q K^T (fp16 single-term) -----------------
#define QKS 72
#define QK_Q 0
#define QK_K (QK_Q + 128 * QKS * 2)
#define QK_SMEM (QK_K + 128 * QKS * 2)    // 36864 bytes

__global__ __launch_bounds__(256) void qk_kernel()
{
    extern __shared__ char sm[];
    __half* Qs = (__half*)(sm + QK_Q);
    __half* Ks = (__half*)(sm + QK_K);

    const int tid = threadIdx.x, lane = tid & 31, warp = tid >> 5;
    const int wm = warp & 3, wn = warp >> 2;
    const int h = blockIdx.z;
    const int q0 = blockIdx.y * 128, k0 = blockIdx.x * 128;
    const int ho = h * DH;

    const int lr = tid >> 2, lc = (tid & 3) * 16;
    #pragma unroll
    for (int it = 0; it < 2; it++) {
        int r = lr + it * 64;
        *(uint4*)&Qs[r * QKS + lc]     = *(const uint4*)&g_Qh[(size_t)(q0 + r) * ND + ho + lc];
        *(uint4*)&Qs[r * QKS + lc + 8] = *(const uint4*)&g_Qh[(size_t)(q0 + r) * ND + ho + lc + 8];
        *(uint4*)&Ks[r * QKS + lc]     = *(const uint4*)&g_Kh[(size_t)(k0 + r) * ND + ho + lc];
        *(uint4*)&Ks[r * QKS + lc + 8] = *(const uint4*)&g_Kh[(size_t)(k0 + r) * ND + ho + lc + 8];
    }
    __syncthreads();

    float acc[2][8][4] = {};
    #pragma unroll
    for (int kk = 0; kk < 64; kk += 16) {
        uint32_t A[2][4];
        int arow = wm * 32 + (lane & 7) + ((lane >> 3) & 1) * 8;
        int acol = kk + (lane >> 4) * 8;
        ldsm4(A[0], smem_u32(&Qs[arow * QKS + acol]));
        ldsm4(A[1], smem_u32(&Qs[(arow + 16) * QKS + acol]));
        #pragma unroll
        for (int nt2 = 0; nt2 < 4; nt2++) {
            uint32_t B[4];
            int brow = wn * 64 + nt2 * 16 + (lane >> 4) * 8 + (lane & 7);
            int bcol = kk + ((lane >> 3) & 1) * 8;
            ldsm4(B, smem_u32(&Ks[brow * QKS + bcol]));
            #pragma unroll
            for (int mt = 0; mt < 2; mt++)
                #pragma unroll
                for (int p = 0; p < 2; p++)
                    mma16816h(acc[mt][nt2 * 2 + p], A[mt], &B[p * 2]);
        }
    }

    __half* out = g_logith + (size_t)h * SEQ * SEQ;
    const int r0 = lane >> 2, cc = (lane & 3) * 2;
    #pragma unroll
    for (int mt = 0; mt < 2; mt++)
        #pragma unroll
        for (int nt = 0; nt < 8; nt++) {
            int m = q0 + wm * 32 + mt * 16 + r0;
            int n = k0 + wn * 64 + nt * 8 + cc;
            *(__half2*)&out[(size_t)m * SEQ + n] =
                __floats2half2_rn(acc[mt][nt][0] * 0.125f, acc[mt][nt][1] * 0.125f);
            *(__half2*)&out[(size_t)(m + 8) * SEQ + n] =
                __floats2half2_rn(acc[mt][nt][2] * 0.125f, acc[mt][nt][3] * 0.125f);
        }
}

// -------- li[h,q,n] = sum_d Q[q, h*64+d] * pos_emb[d, n] --------------------
__global__ __launch_bounds__(256) void li_kernel(const float* __restrict__ pos_emb)
{
    __shared__ float Qs[64][65];
    __shared__ float Ps[64][65];
    const int tid = threadIdx.x;
    const int tx = tid & 15, ty = tid >> 4;
    const int h = blockIdx.y;
    const int q0 = blockIdx.x * 64;

    for (int i = tid; i < 64 * 64; i += 256) {
        int r = i >> 6, c = i & 63;
        Qs[r][c] = g_Q[(q0 + r) * ND + h * DH + c];
        Ps[r][c] = pos_emb[r * NPOS + c];
    }
    __syncthreads();

    float acc[4][4] = {};
    #pragma unroll 8
    for (int d = 0; d < 64; d++) {
        float a[4], b[4];
        #pragma unroll
        for (int i = 0; i < 4; i++) a[i] = Qs[ty * 4 + i][d];
        #pragma unroll
        for (int j = 0; j < 4; j++) b[j] = Ps[d][tx * 4 + j];
        #pragma unroll
        for (int i = 0; i < 4; i++)
            #pragma unroll
            for (int j = 0; j < 4; j++) acc[i][j] += a[i] * b[j];
    }
    #pragma unroll
    for (int i = 0; i < 4; i++)
        #pragma unroll
        for (int j = 0; j < 4; j++)
            g_li[(h * SEQ + q0 + ty * 4 + i) * NPOS + tx * 4 + j] = acc[i][j];
}

// -------- per (h,q) row: gates -> suffix-cumsum -> CoPE -> softmax ----------
__global__ __launch_bounds__(256) void cope_softmax_kernel()
{
    __shared__ float li[NPOS];
    __shared__ float wsum[8];
    __shared__ float redm[8];
    __shared__ float reds[8];

    const int tid = threadIdx.x;
    const int lane = tid & 31, warp = tid >> 5;
    const int q = blockIdx.x, h = blockIdx.y;
    const size_t rbase = ((size_t)h * SEQ + q) * SEQ;
    const __half* lrow = g_logith + rbase;

    if (tid < NPOS) li[tid] = g_li[(h * SEQ + q) * NPOS + tid];

    const int base = tid * 8;
    uint4 raw = *(const uint4*)&lrow[base];
    const __half2* hp = (const __half2*)&raw;
    float x[8];
    {
        float2 f0 = __half22float2(hp[0]);
        float2 f1 = __half22float2(hp[1]);
        float2 f2 = __half22float2(hp[2]);
        float2 f3 = __half22float2(hp[3]);
        x[0] = f0.x; x[1] = f0.y; x[2] = f1.x; x[3] = f1.y;
        x[4] = f2.x; x[5] = f2.y; x[6] = f3.x; x[7] = f3.y;
    }

    float g[8];
    float csum = 0.0f;
    #pragma unroll
    for (int j = 7; j >= 0; --j) {
        float t;
        asm("tanh.approx.f32 %0, %1;" : "=f"(t) : "f"(x[j] * 0.5f));
        csum += fmaf(t, 0.5f, 0.5f);
        g[j] = csum;
    }
    float v = csum;
    #pragma unroll
    for (int d = 1; d < 32; d <<= 1) {
        float n = __shfl_up_sync(0xffffffffu, v, d);
        if (lane >= d) v += n;
    }
    if (lane == 31) wsum[warp] = v;
    __syncthreads();
    float wpre = 0.0f, total = 0.0f;
    #pragma unroll
    for (int w = 0; w < 8; w++) {
        float s = wsum[w];
        if (w < warp) wpre += s;
        total += s;
    }
    const float off = total - (wpre + v);

    float lmax = -INFINITY;
    #pragma unroll
    for (int j = 0; j < 8; j++) {
        float pos = fminf(g[j] + off, (float)(NPOS - 1));
        float pf = floorf(pos);
        int fi = (int)pf;
        int ci = (int)ceilf(pos);
        float w = pos - pf;
        x[j] += li[ci] * w + li[fi] * (1.0f - w);
        lmax = fmaxf(lmax, x[j]);
    }
    #pragma unroll
    for (int d = 16; d > 0; d >>= 1)
        lmax = fmaxf(lmax, __shfl_xor_sync(0xffffffffu, lmax, d));
    if (lane == 0) redm[warp] = lmax;
    __syncthreads();
    float mx = redm[0];
    #pragma unroll
    for (int w = 1; w < 8; w++) mx = fmaxf(mx, redm[w]);

    float lsum = 0.0f;
    #pragma unroll
    for (int j = 0; j < 8; j++) {
        x[j] = __expf(x[j] - mx);
        lsum += x[j];
    }
    #pragma unroll
    for (int d = 16; d > 0; d >>= 1)
        lsum += __shfl_xor_sync(0xffffffffu, lsum, d);
    if (lane == 0) reds[warp] = lsum;
    __syncthreads();
    float tsum = 0.0f;
    #pragma unroll
    for (int w = 0; w < 8; w++) tsum += reds[w];
    const float inv = 1.0f / tsum;

    __half hs[8];
    #pragma unroll
    for (int j = 0; j < 8; j++) hs[j] = __float2half_rn(x[j] * inv);
    *(uint4*)&g_Sf[rbase + base] = *(uint4*)hs;
}

// -------- ctx = S(fp16) @ V(fp16 hi/lo), cp.async 3-stage -------------------
#define CXST  40
#define CXVST 72
#define CX_S  0
#define CX_VH (128 * CXST)
#define CX_VL (128 * CXST + 32 * CXVST)
#define CX_STAGE (128 * CXST + 64 * CXVST)
#define CX_SMEM  (3 * CX_STAGE * 2)          // 58368 bytes

__global__ __launch_bounds__(256, 2) void ctx_kernel()
{
    extern __shared__ __half cxs[];
    const int tid = threadIdx.x, lane = tid & 31, warp = tid >> 5;
    const int wm = warp & 3, wn = warp >> 2;
    const int h = blockIdx.y;
    const int q0 = blockIdx.x * 128;
    const int ho = h * DH;
    const __half* Sf = g_Sf + (size_t)h * SEQ * SEQ;

    const int sr = tid >> 1, sc = (tid & 1) * 16;
    const int vr = tid >> 3, vc = (tid & 7) * 8;

    #define CX_LOAD(kt, s)                                                        \
        { __half* st = cxs + (s) * CX_STAGE;                                      \
          cp16(smem_u32(&st[CX_S + sr * CXST + sc]),                              \
               &Sf[(size_t)(q0 + sr) * SEQ + (kt) + sc]);                         \
          cp16(smem_u32(&st[CX_S + sr * CXST + sc + 8]),                          \
               &Sf[(size_t)(q0 + sr) * SEQ + (kt) + sc + 8]);                     \
          cp16(smem_u32(&st[CX_VH + vr * CXVST + vc]),                            \
               &g_Vh[(size_t)((kt) + vr) * ND + ho + vc]);                        \
          cp16(smem_u32(&st[CX_VL + vr * CXVST + vc]),                            \
               &g_Vl[(size_t)((kt) + vr) * ND + ho + vc]);                        \
          CP_COMMIT(); }

    float acc[2][4][4] = {};
    CX_LOAD(0, 0);
    CX_LOAD(32, 1);
    int s = 0;
    for (int kt = 0; kt < SEQ; kt += 32) {
        if (kt + 64 < SEQ) {
            int sn = s + 2; if (sn >= 3) sn -= 3;
            CX_LOAD(kt + 64, sn);
            CP_WAIT2();
        } else if (kt + 32 < SEQ) {
            CP_WAIT1();
        } else {
            CP_WAIT0();
        }
        __syncthreads();
        __half* st = cxs + s * CX_STAGE;
        #pragma unroll
        for (int kk = 0; kk < 32; kk += 16) {
            uint32_t A[2][4];
            int arow = wm * 32 + (lane & 7) + ((lane >> 3) & 1) * 8;
            int acol = kk + (lane >> 4) * 8;
            ldsm4(A[0], smem_u32(&st[CX_S + arow * CXST + acol]));
            ldsm4(A[1], smem_u32(&st[CX_S + (arow + 16) * CXST + acol]));
            #pragma unroll
            for (int nt2 = 0; nt2 < 2; nt2++) {
                uint32_t Bh[4], Bl[4];
                int vrow = kk + ((lane >> 3) & 1) * 8 + (lane & 7);
                int vcol = wn * 32 + nt2 * 16 + (lane >> 4) * 8;
                ldsm4t(Bh, smem_u32(&st[CX_VH + vrow * CXVST + vcol]));
                ldsm4t(Bl, smem_u32(&st[CX_VL + vrow * CXVST + vcol]));
                #pragma unroll
                for (int mt = 0; mt < 2; mt++)
                    #pragma unroll
                    for (int p = 0; p < 2; p++) {
                        mma16816h(acc[mt][nt2 * 2 + p], A[mt], &Bh[p * 2]);
                        mma16816h(acc[mt][nt2 * 2 + p], A[mt], &Bl[p * 2]);
                    }
            }
        }
        __syncthreads();
        s = (s + 1 >= 3) ? 0 : s + 1;
    }

    const int r0 = lane >> 2, cc = (lane & 3) * 2;
    #pragma unroll
    for (int mt = 0; mt < 2; mt++)
        #pragma unroll
        for (int nt = 0; nt < 4; nt++) {
            int m = q0 + wm * 32 + mt * 16 + r0;
            int n = ho + wn * 32 + nt * 8 + cc;
            float v0 = acc[mt][nt][0], v1 = acc[mt][nt][1];
            float v2 = acc[mt][nt][2], v3 = acc[mt][nt][3];
            bf16 h0 = __float2bfloat16_rn(v0), h1 = __float2bfloat16_rn(v1);
            bf16 h2 = __float2bfloat16_rn(v2), h3 = __float2bfloat16_rn(v3);
            *(bf162*)&g_ctxh[(size_t)m * ND + n]       = bf162{h0, h1};
            *(bf162*)&g_ctxh[(size_t)(m + 8) * ND + n] = bf162{h2, h3};
            *(bf162*)&g_ctxl[(size_t)m * ND + n] =
                bf162{__float2bfloat16_rn(v0 - __bfloat162float(h0)),
                      __float2bfloat16_rn(v1 - __bfloat162float(h1))};
            *(bf162*)&g_ctxl[(size_t)(m + 8) * ND + n] =
                bf162{__float2bfloat16_rn(v2 - __bfloat162float(h2)),
                      __float2bfloat16_rn(v3 - __bfloat162float(h3))};
        }
}

// ---------------------------------------------------------------------------
extern "C" void kernel_launch(void* const* d_in, const int* in_sizes, int n_in,
                              void* d_out, int out_size)
{
    const float* q      = (const float*)d_in[0];
    const float* k      = (const float*)d_in[1];
    const float* v      = (const float*)d_in[2];
    const float* Wq_w   = (const float*)d_in[3];
    const float* Wq_b   = (const float*)d_in[4];
    const float* Wk_w   = (const float*)d_in[5];
    const float* Wk_b   = (const float*)d_in[6];
    const float* Wv_w   = (const float*)d_in[7];
    const float* Wv_b   = (const float*)d_in[8];
    const float* Wo_w   = (const float*)d_in[9];
    const float* Wo_b   = (const float*)d_in[10];
    const float* pos_emb= (const float*)d_in[11];
    float* out = (float*)d_out;

    static bool attr_set = false;
    if (!attr_set) {
        cudaFuncSetAttribute(mm_bias_kernel,
                             cudaFuncAttributeMaxDynamicSharedMemorySize, MM_SMEM);
        cudaFuncSetAttribute(qk_kernel,
                             cudaFuncAttributeMaxDynamicSharedMemorySize, QK_SMEM);
        cudaFuncSetAttribute(ctx_kernel,
                             cudaFuncAttributeMaxDynamicSharedMemorySize, CX_SMEM);
        attr_set = true;
    }

    bf16 *inqh, *inql, *inkh, *inkl, *invh, *invl;
    bf16 *wqh, *wql, *wkh, *wkl, *wvh, *wvl, *woh, *wol;
    bf16 *ctxh, *ctxl;
    __half *Qh, *Ql, *Kh, *Kl, *Vh, *Vl;
    float* Qf;
    cudaGetSymbolAddress((void**)&inqh, g_inqh); cudaGetSymbolAddress((void**)&inql, g_inql);
    cudaGetSymbolAddress((void**)&inkh, g_inkh); cudaGetSymbolAddress((void**)&inkl, g_inkl);
    cudaGetSymbolAddress((void**)&invh, g_invh); cudaGetSymbolAddress((void**)&invl, g_invl);
    cudaGetSymbolAddress((void**)&wqh, g_wqh);   cudaGetSymbolAddress((void**)&wql, g_wql);
    cudaGetSymbolAddress((void**)&wkh, g_wkh);   cudaGetSymbolAddress((void**)&wkl, g_wkl);
    cudaGetSymbolAddress((void**)&wvh, g_wvh);   cudaGetSymbolAddress((void**)&wvl, g_wvl);
    cudaGetSymbolAddress((void**)&woh, g_woh);   cudaGetSymbolAddress((void**)&wol, g_wol);
    cudaGetSymbolAddress((void**)&Qh, g_Qh);     cudaGetSymbolAddress((void**)&Ql, g_Ql);
    cudaGetSymbolAddress((void**)&Kh, g_Kh);     cudaGetSymbolAddress((void**)&Kl, g_Kl);
    cudaGetSymbolAddress((void**)&Vh, g_Vh);     cudaGetSymbolAddress((void**)&Vl, g_Vl);
    cudaGetSymbolAddress((void**)&ctxh, g_ctxh); cudaGetSymbolAddress((void**)&ctxl, g_ctxl);
    cudaGetSymbolAddress((void**)&Qf, g_Q);

    const int nIn = SEQ * ND / 1024;
    const int nW  = ND * ND / 1024;

    split3_kernel<<<dim3(nIn, 3), 256>>>(q, k, v,
                                         inqh, inql, inkh, inkl, invh, invl);
    split4_kernel<<<dim3(nW, 4), 256>>>(Wq_w, Wk_w, Wv_w, Wo_w,
                                        wqh, wql, wkh, wkl, wvh, wvl, woh, wol);

    MMJob jq{inqh, inql, wqh, wql, Wq_b, Qf, Qh, Ql, 1};
    MMJob jk{inkh, inkl, wkh, wkl, Wk_b, nullptr, Kh, Kl, 1};
    MMJob jv{invh, invl, wvh, wvl, Wv_b, nullptr, Vh, Vl, 1};
    MMJob jo{ctxh, ctxl, woh, wol, Wo_b, out, nullptr, nullptr, 0};

    dim3 gProj3(ND / 64, SEQ / 128, 3);   // 768 CTAs
    mm_bias_kernel<<<gProj3, 256, MM_SMEM>>>(jq, jk, jv);

    qk_kernel<<<dim3(SEQ / 128, SEQ / 128, NH), 256, QK_SMEM>>>();
    li_kernel<<<dim3(SEQ / 64, NH), 256>>>(pos_emb);
    cope_softmax_kernel<<<dim3(SEQ, NH), 256>>>();
    ctx_kernel<<<dim3(SEQ / 128, NH), 256, CX_SMEM>>>();

    dim3 gProj1(ND / 64, SEQ / 128, 1);
    mm_bias_kernel<<<gProj1, 256, MM_SMEM>>>(jo, jo, jo);
}